// round 13
// baseline (speedup 1.0000x reference)
#include <cuda_runtime.h>

#define B_    4096
#define NTOK  49
#define DIMC  192
#define NH    6
#define HD    32
#define NWIN  64

#define BM  128
#define BN  64
#define BKC 16
#define NCH (DIMC / BKC)   // 12 k-chunks
#define AST 24             // u32 stride per SMEM row (conflict-free fragments)

typedef unsigned long long u64;
typedef unsigned int u32;

// Scratch (device globals — allocation-free per harness rules)
__device__ float g_q[(size_t)B_ * NH * NTOK * HD];   // q pre-scaled by hd^-0.5
__device__ float g_k[(size_t)B_ * NH * NTOK * HD];
__device__ float g_v[(size_t)B_ * NH * NTOK * HD];
__device__ float g_ctx[(size_t)B_ * NTOK * DIMC];

#define BMS 52   // bm row stride (float4-aligned blocks of 4)
__device__ float g_bm[(size_t)NWIN * NH * NTOK * BMS];  // rpb-gather + mask, precomputed

__device__ __forceinline__ u32 f2tf(float f) {
    u32 r; asm("cvt.rna.tf32.f32 %0, %1;" : "=r"(r) : "f"(f)); return r;
}
__device__ __forceinline__ void mma_tf32(float* d, u32 a0, u32 a1, u32 a2, u32 a3,
                                         u32 b0, u32 b1) {
    asm volatile(
        "mma.sync.aligned.m16n8k8.row.col.f32.tf32.tf32.f32 "
        "{%0,%1,%2,%3}, {%4,%5,%6,%7}, {%8,%9}, {%0,%1,%2,%3};"
        : "+f"(d[0]), "+f"(d[1]), "+f"(d[2]), "+f"(d[3])
        : "r"(a0), "r"(a1), "r"(a2), "r"(a3), "r"(b0), "r"(b1));
}
__device__ __forceinline__ void ffma2(u64& acc, u64 a, u64 b) {
    asm("fma.rn.f32x2 %0, %1, %2, %0;" : "+l"(acc) : "l"(a), "l"(b));
}

// ===========================================================================
// tf32 MMA GEMM mainloop (unchanged — working)
// ===========================================================================
#define TF32_GEMM_MAINLOOP(XPTR, WPTR)                                         \
    __shared__ __align__(16) u32 As[2][BM * AST];                              \
    __shared__ __align__(16) u32 Bs[2][BN * AST];                              \
    const int tid   = threadIdx.x;                                             \
    const int lane  = tid & 31;                                                \
    const int wid   = tid >> 5;                                                \
    const int m0    = blockIdx.y * BM;                                         \
    const int j0    = blockIdx.x * BN;                                         \
    const int ldrow = tid >> 2;                                                \
    const int ldcg  = tid & 3;                                                 \
    const int ldoff = (ldcg & 1) + (ldcg >> 1) * 8;                            \
    const int frow  = lane >> 2;                                               \
    const int fcol  = lane & 3;                                                \
    const int wm    = wid * 32;                                                \
    float acc[2][8][4];                                                        \
    _Pragma("unroll") for (int i = 0; i < 2; i++)                              \
        _Pragma("unroll") for (int j = 0; j < 8; j++)                          \
            _Pragma("unroll") for (int e = 0; e < 4; e++) acc[i][j][e] = 0.f;  \
    float4 aR[4]; float4 bR[2];                                                \
    _Pragma("unroll") for (int s = 0; s < 4; s++)                              \
        aR[s] = *reinterpret_cast<const float4*>(                              \
            XPTR + (size_t)(m0 + s * 32 + ldrow) * DIMC + ldcg * 4);           \
    _Pragma("unroll") for (int s = 0; s < 2; s++)                              \
        bR[s] = *reinterpret_cast<const float4*>(                              \
            WPTR + (size_t)(j0 + s * 32 + ldrow) * DIMC + ldcg * 4);           \
    _Pragma("unroll") for (int s = 0; s < 4; s++) {                            \
        const int ba = (s * 32 + ldrow) * AST + ldoff;                         \
        As[0][ba + 0] = f2tf(aR[s].x); As[0][ba + 2] = f2tf(aR[s].y);          \
        As[0][ba + 4] = f2tf(aR[s].z); As[0][ba + 6] = f2tf(aR[s].w);          \
    }                                                                          \
    _Pragma("unroll") for (int s = 0; s < 2; s++) {                            \
        const int ba = (s * 32 + ldrow) * AST + ldoff;                         \
        Bs[0][ba + 0] = f2tf(bR[s].x); Bs[0][ba + 2] = f2tf(bR[s].y);          \
        Bs[0][ba + 4] = f2tf(bR[s].z); Bs[0][ba + 6] = f2tf(bR[s].w);          \
    }                                                                          \
    __syncthreads();                                                           \
    for (int t = 0; t < NCH; t++) {                                            \
        const int buf = t & 1;                                                 \
        if (t + 1 < NCH) {                                                     \
            const int kb = (t + 1) * BKC;                                      \
            _Pragma("unroll") for (int s = 0; s < 4; s++)                      \
                aR[s] = *reinterpret_cast<const float4*>(                      \
                    XPTR + (size_t)(m0 + s * 32 + ldrow) * DIMC + kb + ldcg * 4); \
            _Pragma("unroll") for (int s = 0; s < 2; s++)                      \
                bR[s] = *reinterpret_cast<const float4*>(                      \
                    WPTR + (size_t)(j0 + s * 32 + ldrow) * DIMC + kb + ldcg * 4); \
        }                                                                      \
        _Pragma("unroll") for (int ks = 0; ks < 2; ks++) {                     \
            uint2 afr[2][2];                                                   \
            _Pragma("unroll") for (int am = 0; am < 2; am++) {                 \
                const int r0 = wm + am * 16 + frow;                            \
                afr[am][0] = *reinterpret_cast<const uint2*>(                  \
                    &As[buf][r0 * AST + (ks * 4 + fcol) * 2]);                 \
                afr[am][1] = *reinterpret_cast<const uint2*>(                  \
                    &As[buf][(r0 + 8) * AST + (ks * 4 + fcol) * 2]);           \
            }                                                                  \
            uint2 bfr[8];                                                      \
            _Pragma("unroll") for (int an = 0; an < 8; an++)                   \
                bfr[an] = *reinterpret_cast<const uint2*>(                     \
                    &Bs[buf][(an * 8 + frow) * AST + (ks * 4 + fcol) * 2]);    \
            _Pragma("unroll") for (int am = 0; am < 2; am++)                   \
                _Pragma("unroll") for (int an = 0; an < 8; an++)               \
                    mma_tf32(acc[am][an],                                      \
                             afr[am][0].x, afr[am][1].x,                       \
                             afr[am][0].y, afr[am][1].y,                       \
                             bfr[an].x, bfr[an].y);                            \
        }                                                                      \
        if (t + 1 < NCH) {                                                     \
            const int nb = (t + 1) & 1;                                        \
            _Pragma("unroll") for (int s = 0; s < 4; s++) {                    \
                const int ba = (s * 32 + ldrow) * AST + ldoff;                 \
                As[nb][ba + 0] = f2tf(aR[s].x); As[nb][ba + 2] = f2tf(aR[s].y); \
                As[nb][ba + 4] = f2tf(aR[s].z); As[nb][ba + 6] = f2tf(aR[s].w); \
            }                                                                  \
            _Pragma("unroll") for (int s = 0; s < 2; s++) {                    \
                const int ba = (s * 32 + ldrow) * AST + ldoff;                 \
                Bs[nb][ba + 0] = f2tf(bR[s].x); Bs[nb][ba + 2] = f2tf(bR[s].y); \
                Bs[nb][ba + 4] = f2tf(bR[s].z); Bs[nb][ba + 6] = f2tf(bR[s].w); \
            }                                                                  \
            __syncthreads();                                                   \
        }                                                                      \
    }

// ---------------------------------------------------------------------------
// Kernel 0: precompute bias+mask table
// ---------------------------------------------------------------------------
__global__ __launch_bounds__(256)
void bias_kernel(const float* __restrict__ mask,
                 const float* __restrict__ rpb,
                 const int*   __restrict__ rel_idx)
{
    const int wh = blockIdx.x;
    const int w  = wh / NH;
    const int h  = wh - w * NH;
    float* dst = g_bm + (size_t)wh * (NTOK * BMS);
    const float* msk = mask + (size_t)w * (NTOK * NTOK);
    for (int idx = threadIdx.x; idx < NTOK * NTOK; idx += 256) {
        const int i = idx / NTOK;
        const int j = idx - i * NTOK;
        dst[i * BMS + j] = rpb[rel_idx[idx] * NH + h] + msk[idx];
    }
}

// ---------------------------------------------------------------------------
// Kernel 1: QKV GEMM + bias, scatter into g_q/g_k/g_v [B,H,N,hd], q *= scale
// ---------------------------------------------------------------------------
__global__ __launch_bounds__(128, 3)
void qkv_gemm_kernel(const float* __restrict__ X,
                     const float* __restrict__ W,
                     const float* __restrict__ bias)
{
    TF32_GEMM_MAINLOOP(X, W)

    const int tt = j0 / DIMC;
    const int r0 = j0 - tt * DIMC;
    float* dstArr = (tt == 0) ? g_q : ((tt == 1) ? g_k : g_v);
    const float mul = (tt == 0) ? 0.17677669529663687f : 1.0f;

#pragma unroll
    for (int an = 0; an < 8; an++) {
        const int jc = an * 8 + fcol * 2;
        const float bx = bias[j0 + jc];
        const float by = bias[j0 + jc + 1];
        const int c = r0 + jc;
        const int h = c >> 5;
        const int d = c & 31;
#pragma unroll
        for (int am = 0; am < 2; am++) {
#pragma unroll
            for (int rh = 0; rh < 2; rh++) {
                const int m  = m0 + wm + am * 16 + frow + rh * 8;
                const int bi = m / NTOK;
                const int ni = m - bi * NTOK;
                const size_t dst = ((size_t)(bi * NH + h) * NTOK + ni) * HD + d;
                float2 o;
                o.x = (acc[am][an][rh * 2 + 0] + bx) * mul;
                o.y = (acc[am][an][rh * 2 + 1] + by) * mul;
                *reinterpret_cast<float2*>(&dstArr[dst]) = o;
            }
        }
    }
}

// ---------------------------------------------------------------------------
// Kernel 3: output projection  out = ctx @ proj_w.T + proj_b
// ---------------------------------------------------------------------------
__global__ __launch_bounds__(128, 3)
void proj_gemm_kernel(const float* __restrict__ W,
                      const float* __restrict__ bias,
                      float* __restrict__ out)
{
    const float* Xg = g_ctx;
    TF32_GEMM_MAINLOOP(Xg, W)

#pragma unroll
    for (int an = 0; an < 8; an++) {
        const int jc = an * 8 + fcol * 2;
        const float bx = bias[j0 + jc];
        const float by = bias[j0 + jc + 1];
#pragma unroll
        for (int am = 0; am < 2; am++) {
#pragma unroll
            for (int rh = 0; rh < 2; rh++) {
                const int m = m0 + wm + am * 16 + frow + rh * 8;
                float2 o;
                o.x = acc[am][an][rh * 2 + 0] + bx;
                o.y = acc[am][an][rh * 2 + 1] + by;
                *reinterpret_cast<float2*>(&out[(size_t)m * DIMC + j0 + jc]) = o;
            }
        }
    }
}

// ---------------------------------------------------------------------------
// Kernel 2: per-(window, head) attention.
// S: 4x4 f32x2 register blocking -> non-duplicated S (SMEM 30KB, 7 blocks/SM).
// softmax+PV fused per warp on contiguous row ranges (2 barriers total).
// ---------------------------------------------------------------------------
#define QSTR 34
#define SST  52

__global__ __launch_bounds__(256)
void attn_kernel(float* __restrict__ attn_out)
{
    __shared__ float qs[NTOK * QSTR];
    __shared__ float ks[NTOK * QSTR];
    __shared__ float vs[NTOK * QSTR];
    __shared__ float S[NTOK * SST];

    const int bh  = blockIdx.x;
    const int b   = bh / NH;
    const int h   = bh - b * NH;
    const int tid = threadIdx.x;

    // ---- stage q/k/v as float2 ----
    const size_t base2 = (size_t)bh * (NTOK * HD / 2);
    const float2* q2 = reinterpret_cast<const float2*>(g_q) + base2;
    const float2* k2 = reinterpret_cast<const float2*>(g_k) + base2;
    const float2* v2 = reinterpret_cast<const float2*>(g_v) + base2;
    for (int idx = tid; idx < NTOK * (HD / 2); idx += 256) {
        const int r = idx >> 4, dp = idx & 15;
        *reinterpret_cast<float2*>(&qs[r * QSTR + 2 * dp]) = q2[idx];
        *reinterpret_cast<float2*>(&ks[r * QSTR + 2 * dp]) = k2[idx];
        *reinterpret_cast<float2*>(&vs[r * QSTR + 2 * dp]) = v2[idx];
    }
    __syncthreads();

    // ---- S = q k^T + bm : 4x4 register-blocked, one task per thread ----
    const float* bm = g_bm + (size_t)((b & (NWIN - 1)) * NH + h) * (NTOK * BMS);
    if (tid < 13 * 13) {
        const int bi = tid / 13, bj = tid - 13 * (tid / 13);
        const int i0 = bi * 4, j0 = bj * 4;
        const u64* qp[4]; const u64* kp[4];
#pragma unroll
        for (int t = 0; t < 4; t++) {
            const int ri = (i0 + t < NTOK) ? (i0 + t) : (NTOK - 1);
            const int rj = (j0 + t < NTOK) ? (j0 + t) : (NTOK - 1);
            qp[t] = reinterpret_cast<const u64*>(&qs[ri * QSTR]);
            kp[t] = reinterpret_cast<const u64*>(&ks[rj * QSTR]);
        }
        u64 acc[4][4];
#pragma unroll
        for (int a = 0; a < 4; a++)
#pragma unroll
            for (int c = 0; c < 4; c++) acc[a][c] = 0ull;
#pragma unroll
        for (int d = 0; d < HD / 2; d++) {
            u64 qv[4], kv[4];
#pragma unroll
            for (int t = 0; t < 4; t++) { qv[t] = qp[t][d]; kv[t] = kp[t][d]; }
#pragma unroll
            for (int a = 0; a < 4; a++)
#pragma unroll
                for (int c = 0; c < 4; c++)
                    ffma2(acc[a][c], qv[a], kv[c]);
        }
#pragma unroll
        for (int a = 0; a < 4; a++) {
            const int i = i0 + a;
            if (i < NTOK) {
                const float4 bmv = *reinterpret_cast<const float4*>(&bm[i * BMS + j0]);
                const float bb[4] = {bmv.x, bmv.y, bmv.z, bmv.w};
#pragma unroll
                for (int c = 0; c < 4; c++) {
                    if (j0 + c < NTOK) {
                        float2 f = *reinterpret_cast<float2*>(&acc[a][c]);
                        S[i * SST + (j0 + c)] = f.x + f.y + bb[c];
                    }
                }
            }
        }
    }
    __syncthreads();

    // ---- fused softmax + PV, per warp on contiguous rows ----
    const int lane = tid & 31;
    const int wid  = tid >> 5;
    const int rbeg = wid * 6;
    const int rend = (wid == 7) ? NTOK : rbeg + 6;   // warp 7: rows 42..48

    // softmax (lane covers j=lane and j=lane+32)
    for (int i = rbeg; i < rend; i++) {
        float* srow = &S[i * SST];
        const float v1 = srow[lane];
        const float v2 = (lane < NTOK - 32) ? srow[lane + 32] : -3.4e38f;
        float mval = fmaxf(v1, v2);
#pragma unroll
        for (int o = 16; o > 0; o >>= 1)
            mval = fmaxf(mval, __shfl_xor_sync(0xffffffffu, mval, o));
        const float e1 = __expf(v1 - mval);
        const float e2 = (lane < NTOK - 32) ? __expf(v2 - mval) : 0.f;
        float sum = e1 + e2;
#pragma unroll
        for (int o = 16; o > 0; o >>= 1)
            sum += __shfl_xor_sync(0xffffffffu, sum, o);
        const float inv = 1.0f / sum;
        const float p1 = e1 * inv;
        const float p2 = e2 * inv;
        srow[lane] = p1;
        if (lane < NTOK - 32) srow[lane + 32] = p2;
        if (attn_out) {
            float* arow = attn_out + (size_t)bh * (NTOK * NTOK) + i * NTOK;
            arow[lane] = p1;
            if (lane < NTOK - 32) arow[lane + 32] = p2;
        }
    }
    __syncwarp();

    // PV: lane = d; rows processed in pairs (p broadcast, v conflict-free)
    for (int i = rbeg; i < rend; i += 2) {
        const bool two = (i + 1 < rend);
        const int i1 = two ? i + 1 : i;
        float a0 = 0.f, a1 = 0.f;
        const float* p0 = &S[i * SST];
        const float* p1 = &S[i1 * SST];
#pragma unroll 7
        for (int j = 0; j < NTOK; j++) {
            const float vv = vs[j * QSTR + lane];
            a0 = fmaf(p0[j], vv, a0);
            a1 = fmaf(p1[j], vv, a1);
        }
        const size_t ob = (size_t)b * NTOK * DIMC + h * HD + lane;
        g_ctx[ob + (size_t)i * DIMC] = a0;
        if (two) g_ctx[ob + (size_t)i1 * DIMC] = a1;
    }
}

// ---------------------------------------------------------------------------
// Launch
// ---------------------------------------------------------------------------
extern "C" void kernel_launch(void* const* d_in, const int* in_sizes, int n_in,
                              void* d_out, int out_size)
{
    const float* x      = (const float*)d_in[0];
    const float* mask   = (const float*)d_in[1];
    const float* qkv_w  = (const float*)d_in[2];
    const float* qkv_b  = (const float*)d_in[3];
    const float* proj_w = (const float*)d_in[4];
    const float* proj_b = (const float*)d_in[5];
    const float* rpb    = (const float*)d_in[6];
    const int*   relidx = (const int*)d_in[7];

    float* out = (float*)d_out;
    const long OUT_ELEMS  = (long)B_ * NTOK * DIMC;          // 38,535,168
    const long ATTN_ELEMS = (long)B_ * NH * NTOK * NTOK;     // 59,006,976
    float* attn_out = nullptr;
    if ((long)out_size >= OUT_ELEMS + ATTN_ELEMS) attn_out = out + OUT_ELEMS;

    bias_kernel<<<NWIN * NH, 256>>>(mask, rpb, relidx);
    qkv_gemm_kernel<<<dim3(576 / BN, (B_ * NTOK) / BM), 128>>>(x, qkv_w, qkv_b);
    attn_kernel<<<B_ * NH, 256>>>(attn_out);
    proj_gemm_kernel<<<dim3(DIMC / BN, (B_ * NTOK) / BM), 128>>>(proj_w, proj_b, out);

    (void)in_sizes; (void)n_in;
}

// round 14
// speedup vs baseline: 1.1053x; 1.1053x over previous
#include <cuda_runtime.h>

#define B_    4096
#define NTOK  49
#define DIMC  192
#define NH    6
#define HD    32
#define NWIN  64

#define BM  128
#define BN  64
#define BKC 16
#define NCH (DIMC / BKC)   // 12 k-chunks
#define AST 24             // u32 stride per SMEM row (conflict-free fragments)

typedef unsigned long long u64;
typedef unsigned int u32;

// Scratch (device globals — allocation-free per harness rules)
__device__ float g_q[(size_t)B_ * NH * NTOK * HD];   // q pre-scaled by hd^-0.5
__device__ float g_k[(size_t)B_ * NH * NTOK * HD];
__device__ float g_v[(size_t)B_ * NH * NTOK * HD];
__device__ u32   g_ctx[(size_t)B_ * NTOK * DIMC];    // attention output, tf32 bits
__device__ u32   g_xc[(size_t)B_ * NTOK * DIMC];     // x pre-converted to tf32
__device__ u32   g_wqkv[3 * DIMC * DIMC];            // qkv_w tf32
__device__ u32   g_wproj[DIMC * DIMC];               // proj_w tf32

#define BMS 52
__device__ float g_bm[(size_t)NWIN * NH * NTOK * BMS];  // rpb-gather + mask

__device__ __forceinline__ u32 f2tf(float f) {
    u32 r; asm("cvt.rna.tf32.f32 %0, %1;" : "=r"(r) : "f"(f)); return r;
}
__device__ __forceinline__ void mma_tf32(float* d, u32 a0, u32 a1, u32 a2, u32 a3,
                                         u32 b0, u32 b1) {
    asm volatile(
        "mma.sync.aligned.m16n8k8.row.col.f32.tf32.tf32.f32 "
        "{%0,%1,%2,%3}, {%4,%5,%6,%7}, {%8,%9}, {%0,%1,%2,%3};"
        : "+f"(d[0]), "+f"(d[1]), "+f"(d[2]), "+f"(d[3])
        : "r"(a0), "r"(a1), "r"(a2), "r"(a3), "r"(b0), "r"(b1));
}
__device__ __forceinline__ void ffma2(u64& acc, u64 a, u64 b) {
    asm("fma.rn.f32x2 %0, %1, %2, %0;" : "+l"(acc) : "l"(a), "l"(b));
}

// ---------------------------------------------------------------------------
// Kernel P: fp32 -> tf32 bit pre-conversion (grid-stride over float4)
// ---------------------------------------------------------------------------
__global__ __launch_bounds__(256)
void cvt_kernel(const float4* __restrict__ src, uint4* __restrict__ dst, int n4)
{
    for (int i = blockIdx.x * 256 + threadIdx.x; i < n4; i += gridDim.x * 256) {
        const float4 v = src[i];
        uint4 o;
        o.x = f2tf(v.x); o.y = f2tf(v.y); o.z = f2tf(v.z); o.w = f2tf(v.w);
        dst[i] = o;
    }
}

// ===========================================================================
// tf32 MMA GEMM mainloop v2: inputs pre-converted (u32 tf32 bits).
// Fill: coalesced LDG.128 + 2 butterfly shfls -> conflict-free STS.128 into
// the k-pair-permuted layout (slots q..q+3 hold k {q0, q0+4, q0+1, q0+5}).
// Fragment LDS layout identical to the proven R9 core.
// ===========================================================================
#define TF32_GEMM_MAINLOOP(XPTR, WPTR)                                         \
    __shared__ __align__(16) u32 As[2][BM * AST];                              \
    __shared__ __align__(16) u32 Bs[2][BN * AST];                              \
    const int tid   = threadIdx.x;                                             \
    const int lane  = tid & 31;                                                \
    const int wid   = tid >> 5;                                                \
    const int m0    = blockIdx.y * BM;                                         \
    const int j0    = blockIdx.x * BN;                                         \
    const int frow  = lane >> 2;                                               \
    const int fcol  = lane & 3;                                                \
    const int wm    = wid * 32;                                                \
    /* fill-mapping: phase p in {0,1,2,3} -> base rows {0,1,4,5}; j>>2 adds 2 */\
    const int fp    = lane >> 3;                                               \
    const int fj    = lane & 7;                                                \
    const int rbase = (fp & 1) + ((fp >> 1) << 2) + ((fj >> 2) << 1);          \
    const int qq    = (fj & 3) * 4;                                            \
    const bool oddj = (fj & 1);                                                \
    float acc[2][8][4];                                                        \
    _Pragma("unroll") for (int i = 0; i < 2; i++)                              \
        _Pragma("unroll") for (int j = 0; j < 8; j++)                          \
            _Pragma("unroll") for (int e = 0; e < 4; e++) acc[i][j][e] = 0.f;  \
    uint4 aR[4]; uint4 bR[2];                                                  \
    _Pragma("unroll") for (int s = 0; s < 4; s++) {                            \
        const int row = wm + s * 8 + rbase;                                    \
        aR[s] = *reinterpret_cast<const uint4*>(XPTR + (size_t)(m0 + row) * DIMC + qq); \
    }                                                                          \
    _Pragma("unroll") for (int s = 0; s < 2; s++) {                            \
        const int row = wid * 16 + s * 8 + rbase;                              \
        bR[s] = *reinterpret_cast<const uint4*>(WPTR + (size_t)(j0 + row) * DIMC + qq); \
    }                                                                          \
    _Pragma("unroll") for (int s = 0; s < 4; s++) {                            \
        const u32 s1 = __shfl_xor_sync(0xffffffffu, oddj ? aR[s].x : aR[s].z, 1); \
        const u32 s2 = __shfl_xor_sync(0xffffffffu, oddj ? aR[s].y : aR[s].w, 1); \
        const uint4 o = oddj ? make_uint4(s1, aR[s].z, s2, aR[s].w)            \
                             : make_uint4(aR[s].x, s1, aR[s].y, s2);           \
        const int row = wm + s * 8 + rbase;                                    \
        *reinterpret_cast<uint4*>(&As[0][row * AST + qq]) = o;                 \
    }                                                                          \
    _Pragma("unroll") for (int s = 0; s < 2; s++) {                            \
        const u32 s1 = __shfl_xor_sync(0xffffffffu, oddj ? bR[s].x : bR[s].z, 1); \
        const u32 s2 = __shfl_xor_sync(0xffffffffu, oddj ? bR[s].y : bR[s].w, 1); \
        const uint4 o = oddj ? make_uint4(s1, bR[s].z, s2, bR[s].w)            \
                             : make_uint4(bR[s].x, s1, bR[s].y, s2);           \
        const int row = wid * 16 + s * 8 + rbase;                              \
        *reinterpret_cast<uint4*>(&Bs[0][row * AST + qq]) = o;                 \
    }                                                                          \
    __syncthreads();                                                           \
    for (int t = 0; t < NCH; t++) {                                            \
        const int buf = t & 1;                                                 \
        if (t + 1 < NCH) {                                                     \
            const int kb = (t + 1) * BKC + qq;                                 \
            _Pragma("unroll") for (int s = 0; s < 4; s++) {                    \
                const int row = wm + s * 8 + rbase;                            \
                aR[s] = *reinterpret_cast<const uint4*>(XPTR + (size_t)(m0 + row) * DIMC + kb); \
            }                                                                  \
            _Pragma("unroll") for (int s = 0; s < 2; s++) {                    \
                const int row = wid * 16 + s * 8 + rbase;                      \
                bR[s] = *reinterpret_cast<const uint4*>(WPTR + (size_t)(j0 + row) * DIMC + kb); \
            }                                                                  \
        }                                                                      \
        _Pragma("unroll") for (int ks = 0; ks < 2; ks++) {                     \
            uint2 afr[2][2];                                                   \
            _Pragma("unroll") for (int am = 0; am < 2; am++) {                 \
                const int r0 = wm + am * 16 + frow;                            \
                afr[am][0] = *reinterpret_cast<const uint2*>(                  \
                    &As[buf][r0 * AST + (ks * 4 + fcol) * 2]);                 \
                afr[am][1] = *reinterpret_cast<const uint2*>(                  \
                    &As[buf][(r0 + 8) * AST + (ks * 4 + fcol) * 2]);           \
            }                                                                  \
            uint2 bfr[8];                                                      \
            _Pragma("unroll") for (int an = 0; an < 8; an++)                   \
                bfr[an] = *reinterpret_cast<const uint2*>(                     \
                    &Bs[buf][(an * 8 + frow) * AST + (ks * 4 + fcol) * 2]);    \
            _Pragma("unroll") for (int am = 0; am < 2; am++)                   \
                _Pragma("unroll") for (int an = 0; an < 8; an++)               \
                    mma_tf32(acc[am][an],                                      \
                             afr[am][0].x, afr[am][1].x,                       \
                             afr[am][0].y, afr[am][1].y,                       \
                             bfr[an].x, bfr[an].y);                            \
        }                                                                      \
        if (t + 1 < NCH) {                                                     \
            const int nb = (t + 1) & 1;                                        \
            _Pragma("unroll") for (int s = 0; s < 4; s++) {                    \
                const u32 s1 = __shfl_xor_sync(0xffffffffu, oddj ? aR[s].x : aR[s].z, 1); \
                const u32 s2 = __shfl_xor_sync(0xffffffffu, oddj ? aR[s].y : aR[s].w, 1); \
                const uint4 o = oddj ? make_uint4(s1, aR[s].z, s2, aR[s].w)    \
                                     : make_uint4(aR[s].x, s1, aR[s].y, s2);   \
                const int row = wm + s * 8 + rbase;                            \
                *reinterpret_cast<uint4*>(&As[nb][row * AST + qq]) = o;        \
            }                                                                  \
            _Pragma("unroll") for (int s = 0; s < 2; s++) {                    \
                const u32 s1 = __shfl_xor_sync(0xffffffffu, oddj ? bR[s].x : bR[s].z, 1); \
                const u32 s2 = __shfl_xor_sync(0xffffffffu, oddj ? bR[s].y : bR[s].w, 1); \
                const uint4 o = oddj ? make_uint4(s1, bR[s].z, s2, bR[s].w)    \
                                     : make_uint4(bR[s].x, s1, bR[s].y, s2);   \
                const int row = wid * 16 + s * 8 + rbase;                      \
                *reinterpret_cast<uint4*>(&Bs[nb][row * AST + qq]) = o;        \
            }                                                                  \
            __syncthreads();                                                   \
        }                                                                      \
    }

// ---------------------------------------------------------------------------
// Kernel 0: precompute bias+mask table
// ---------------------------------------------------------------------------
__global__ __launch_bounds__(256)
void bias_kernel(const float* __restrict__ mask,
                 const float* __restrict__ rpb,
                 const int*   __restrict__ rel_idx)
{
    const int wh = blockIdx.x;
    const int w  = wh / NH;
    const int h  = wh - w * NH;
    float* dst = g_bm + (size_t)wh * (NTOK * BMS);
    const float* msk = mask + (size_t)w * (NTOK * NTOK);
    for (int idx = threadIdx.x; idx < NTOK * NTOK; idx += 256) {
        const int i = idx / NTOK;
        const int j = idx - i * NTOK;
        dst[i * BMS + j] = rpb[rel_idx[idx] * NH + h] + msk[idx];
    }
}

// ---------------------------------------------------------------------------
// Kernel 1: QKV GEMM + bias, scatter into g_q/g_k/g_v [B,H,N,hd], q *= scale
// ---------------------------------------------------------------------------
__global__ __launch_bounds__(128, 3)
void qkv_gemm_kernel(const float* __restrict__ bias)
{
    const u32* Xc = g_xc;
    const u32* Wc = g_wqkv;
    TF32_GEMM_MAINLOOP(Xc, Wc)

    const int tt = j0 / DIMC;
    const int r0 = j0 - tt * DIMC;
    float* dstArr = (tt == 0) ? g_q : ((tt == 1) ? g_k : g_v);
    const float mul = (tt == 0) ? 0.17677669529663687f : 1.0f;

#pragma unroll
    for (int an = 0; an < 8; an++) {
        const int jc = an * 8 + fcol * 2;
        const float bx = bias[j0 + jc];
        const float by = bias[j0 + jc + 1];
        const int c = r0 + jc;
        const int h = c >> 5;
        const int d = c & 31;
#pragma unroll
        for (int am = 0; am < 2; am++) {
#pragma unroll
            for (int rh = 0; rh < 2; rh++) {
                const int m  = m0 + wm + am * 16 + frow + rh * 8;
                const int bi = m / NTOK;
                const int ni = m - bi * NTOK;
                const size_t dst = ((size_t)(bi * NH + h) * NTOK + ni) * HD + d;
                float2 o;
                o.x = (acc[am][an][rh * 2 + 0] + bx) * mul;
                o.y = (acc[am][an][rh * 2 + 1] + by) * mul;
                *reinterpret_cast<float2*>(&dstArr[dst]) = o;
            }
        }
    }
}

// ---------------------------------------------------------------------------
// Kernel 3: output projection  out = ctx @ proj_w.T + proj_b
// ---------------------------------------------------------------------------
__global__ __launch_bounds__(128, 3)
void proj_gemm_kernel(const float* __restrict__ bias,
                      float* __restrict__ out)
{
    const u32* Xc = g_ctx;
    const u32* Wc = g_wproj;
    TF32_GEMM_MAINLOOP(Xc, Wc)

#pragma unroll
    for (int an = 0; an < 8; an++) {
        const int jc = an * 8 + fcol * 2;
        const float bx = bias[j0 + jc];
        const float by = bias[j0 + jc + 1];
#pragma unroll
        for (int am = 0; am < 2; am++) {
#pragma unroll
            for (int rh = 0; rh < 2; rh++) {
                const int m = m0 + wm + am * 16 + frow + rh * 8;
                float2 o;
                o.x = acc[am][an][rh * 2 + 0] + bx;
                o.y = acc[am][an][rh * 2 + 1] + by;
                *reinterpret_cast<float2*>(&out[(size_t)m * DIMC + j0 + jc]) = o;
            }
        }
    }
}

// ---------------------------------------------------------------------------
// Kernel 2: per-(window, head) attention (R12 version — best measured).
// ctx stored as tf32 bits for the proj GEMM.
// ---------------------------------------------------------------------------
#define QSTR 34
#define SSTR 100

__global__ __launch_bounds__(256)
void attn_kernel(float* __restrict__ attn_out)
{
    __shared__ float qs[NTOK * QSTR];
    __shared__ float ks[NTOK * QSTR];
    __shared__ float vs[NTOK * QSTR];
    __shared__ float Sd[NTOK * SSTR];

    const int bh  = blockIdx.x;
    const int b   = bh / NH;
    const int h   = bh - b * NH;
    const int tid = threadIdx.x;

    const size_t base2 = (size_t)bh * (NTOK * HD / 2);
    const float2* q2 = reinterpret_cast<const float2*>(g_q) + base2;
    const float2* k2 = reinterpret_cast<const float2*>(g_k) + base2;
    const float2* v2 = reinterpret_cast<const float2*>(g_v) + base2;
    for (int idx = tid; idx < NTOK * (HD / 2); idx += 256) {
        const int r = idx >> 4, dp = idx & 15;
        *reinterpret_cast<float2*>(&qs[r * QSTR + 2 * dp]) = q2[idx];
        *reinterpret_cast<float2*>(&ks[r * QSTR + 2 * dp]) = k2[idx];
        *reinterpret_cast<float2*>(&vs[r * QSTR + 2 * dp]) = v2[idx];
    }
    __syncthreads();

    const float* bm = g_bm + (size_t)((b & (NWIN - 1)) * NH + h) * (NTOK * BMS);
    if (tid < 13 * 13) {
        const int bi = tid / 13, bj = tid - 13 * (tid / 13);
        const int i0 = bi * 4, j0 = bj * 4;
        const u64* qp[4]; const u64* kp[4];
#pragma unroll
        for (int t = 0; t < 4; t++) {
            const int ri = (i0 + t < NTOK) ? (i0 + t) : (NTOK - 1);
            const int rj = (j0 + t < NTOK) ? (j0 + t) : (NTOK - 1);
            qp[t] = reinterpret_cast<const u64*>(&qs[ri * QSTR]);
            kp[t] = reinterpret_cast<const u64*>(&ks[rj * QSTR]);
        }
        u64 acc[4][4];
#pragma unroll
        for (int a = 0; a < 4; a++)
#pragma unroll
            for (int c = 0; c < 4; c++) acc[a][c] = 0ull;
#pragma unroll
        for (int d = 0; d < HD / 2; d++) {
            u64 qv[4], kv[4];
#pragma unroll
            for (int t = 0; t < 4; t++) { qv[t] = qp[t][d]; kv[t] = kp[t][d]; }
#pragma unroll
            for (int a = 0; a < 4; a++)
#pragma unroll
                for (int c = 0; c < 4; c++)
                    ffma2(acc[a][c], qv[a], kv[c]);
        }
#pragma unroll
        for (int a = 0; a < 4; a++) {
            const int i = i0 + a;
            if (i < NTOK) {
                const float4 bmv = *reinterpret_cast<const float4*>(&bm[i * BMS + j0]);
                const float bb[4] = {bmv.x, bmv.y, bmv.z, bmv.w};
#pragma unroll
                for (int c = 0; c < 4; c++) {
                    if (j0 + c < NTOK) {
                        float2 f = *reinterpret_cast<float2*>(&acc[a][c]);
                        const float s = f.x + f.y + bb[c];
                        float2 dd; dd.x = s; dd.y = s;
                        *reinterpret_cast<float2*>(&Sd[i * SSTR + 2 * (j0 + c)]) = dd;
                    }
                }
            }
        }
    }
    __syncthreads();

    const int lane = tid & 31;
    const int wid  = tid >> 5;
    for (int i = wid; i < NTOK; i += 8) {
        float mval = -3.4e38f;
        for (int j = lane; j < NTOK; j += 32) mval = fmaxf(mval, Sd[i * SSTR + 2 * j]);
#pragma unroll
        for (int o = 16; o > 0; o >>= 1)
            mval = fmaxf(mval, __shfl_xor_sync(0xffffffffu, mval, o));
        float sum = 0.f;
        float ev[2];
        for (int j = lane, c = 0; j < NTOK; j += 32, c++) {
            const float e = __expf(Sd[i * SSTR + 2 * j] - mval);
            ev[c] = e;
            sum += e;
        }
#pragma unroll
        for (int o = 16; o > 0; o >>= 1)
            sum += __shfl_xor_sync(0xffffffffu, sum, o);
        const float inv = 1.0f / sum;
        for (int j = lane, c = 0; j < NTOK; j += 32, c++) {
            const float pv = ev[c] * inv;
            float2 dd; dd.x = pv; dd.y = pv;
            *reinterpret_cast<float2*>(&Sd[i * SSTR + 2 * j]) = dd;
            if (attn_out)
                attn_out[(size_t)bh * (NTOK * NTOK) + i * NTOK + j] = pv;
        }
    }
    __syncthreads();

    // ctx = P V : 4 rows x 4 d-values per thread; store tf32 bits
    if (tid < 13 * 8) {
        const int rb = tid >> 3;
        const int dg = tid & 7;
        const int i0 = rb * 4;
        const int r1 = (i0 + 1 < NTOK) ? i0 + 1 : NTOK - 1;
        const int r2 = (i0 + 2 < NTOK) ? i0 + 2 : NTOK - 1;
        const int r3 = (i0 + 3 < NTOK) ? i0 + 3 : NTOK - 1;
        u64 c00 = 0, c01 = 0, c10 = 0, c11 = 0;
        u64 c20 = 0, c21 = 0, c30 = 0, c31 = 0;
#pragma unroll 7
        for (int j = 0; j < NTOK; j++) {
            const u64 v0 = *reinterpret_cast<const u64*>(&vs[j * QSTR + 4 * dg]);
            const u64 v1 = *reinterpret_cast<const u64*>(&vs[j * QSTR + 4 * dg + 2]);
            const u64 p0 = *reinterpret_cast<const u64*>(&Sd[i0 * SSTR + 2 * j]);
            const u64 p1 = *reinterpret_cast<const u64*>(&Sd[r1 * SSTR + 2 * j]);
            const u64 p2 = *reinterpret_cast<const u64*>(&Sd[r2 * SSTR + 2 * j]);
            const u64 p3 = *reinterpret_cast<const u64*>(&Sd[r3 * SSTR + 2 * j]);
            ffma2(c00, p0, v0); ffma2(c01, p0, v1);
            ffma2(c10, p1, v0); ffma2(c11, p1, v1);
            ffma2(c20, p2, v0); ffma2(c21, p2, v1);
            ffma2(c30, p3, v0); ffma2(c31, p3, v1);
        }
        const size_t ob = (size_t)b * NTOK * DIMC + h * HD + 4 * dg;
        u64 cc[4][2] = {{c00, c01}, {c10, c11}, {c20, c21}, {c30, c31}};
#pragma unroll
        for (int r = 0; r < 4; r++) {
            if (i0 + r < NTOK) {
                float2 lo = *reinterpret_cast<float2*>(&cc[r][0]);
                float2 hi = *reinterpret_cast<float2*>(&cc[r][1]);
                uint4 o;
                o.x = f2tf(lo.x); o.y = f2tf(lo.y);
                o.z = f2tf(hi.x); o.w = f2tf(hi.y);
                *reinterpret_cast<uint4*>(&g_ctx[ob + (size_t)(i0 + r) * DIMC]) = o;
            }
        }
    }
}

// ---------------------------------------------------------------------------
// Launch
// ---------------------------------------------------------------------------
extern "C" void kernel_launch(void* const* d_in, const int* in_sizes, int n_in,
                              void* d_out, int out_size)
{
    const float* x      = (const float*)d_in[0];
    const float* mask   = (const float*)d_in[1];
    const float* qkv_w  = (const float*)d_in[2];
    const float* qkv_b  = (const float*)d_in[3];
    const float* proj_w = (const float*)d_in[4];
    const float* proj_b = (const float*)d_in[5];
    const float* rpb    = (const float*)d_in[6];
    const int*   relidx = (const int*)d_in[7];

    float* out = (float*)d_out;
    const long OUT_ELEMS  = (long)B_ * NTOK * DIMC;          // 38,535,168
    const long ATTN_ELEMS = (long)B_ * NH * NTOK * NTOK;     // 59,006,976
    float* attn_out = nullptr;
    if ((long)out_size >= OUT_ELEMS + ATTN_ELEMS) attn_out = out + OUT_ELEMS;

    u32* d_xc;    cudaGetSymbolAddress((void**)&d_xc,    g_xc);
    u32* d_wqkv;  cudaGetSymbolAddress((void**)&d_wqkv,  g_wqkv);
    u32* d_wproj; cudaGetSymbolAddress((void**)&d_wproj, g_wproj);

    // Pre-convert inputs to tf32 bits
    cvt_kernel<<<4096, 256>>>((const float4*)x, (uint4*)d_xc,
                              (int)(OUT_ELEMS / 4));
    cvt_kernel<<<108, 256>>>((const float4*)qkv_w, (uint4*)d_wqkv,
                             (3 * DIMC * DIMC) / 4);
    cvt_kernel<<<36, 256>>>((const float4*)proj_w, (uint4*)d_wproj,
                            (DIMC * DIMC) / 4);

    bias_kernel<<<NWIN * NH, 256>>>(mask, rpb, relidx);
    qkv_gemm_kernel<<<dim3(576 / BN, (B_ * NTOK) / BM), 128>>>(qkv_b);
    attn_kernel<<<B_ * NH, 256>>>(attn_out);
    proj_gemm_kernel<<<dim3(DIMC / BN, (B_ * NTOK) / BM), 128>>>(proj_b, out);

    (void)in_sizes; (void)n_in;
}

// round 15
// speedup vs baseline: 1.2109x; 1.0956x over previous
#include <cuda_runtime.h>

#define B_    4096
#define NTOK  49
#define DIMC  192
#define NH    6
#define HD    32
#define NWIN  64

#define BM  128
#define BN  64
#define BKC 16
#define NCH (DIMC / BKC)   // 12 k-chunks
#define AST 24             // u32 stride per SMEM row (conflict-free fragments)

typedef unsigned long long u64;
typedef unsigned int u32;

// Scratch (device globals — allocation-free per harness rules)
__device__ float g_q[(size_t)B_ * NH * NTOK * HD];   // q pre-scaled by hd^-0.5
__device__ float g_k[(size_t)B_ * NH * NTOK * HD];
__device__ float g_v[(size_t)B_ * NH * NTOK * HD];
__device__ u32   g_ctx[(size_t)B_ * NTOK * DIMC];    // attention output, tf32 bits
__device__ u32   g_xc[(size_t)B_ * NTOK * DIMC];     // x pre-converted to tf32
__device__ u32   g_wqkv[3 * DIMC * DIMC];            // qkv_w tf32
__device__ u32   g_wproj[DIMC * DIMC];               // proj_w tf32

#define BMS 52
__device__ float g_bm[(size_t)NWIN * NH * NTOK * BMS];  // rpb-gather + mask

__device__ __forceinline__ u32 f2tf(float f) {
    u32 r; asm("cvt.rna.tf32.f32 %0, %1;" : "=r"(r) : "f"(f)); return r;
}
__device__ __forceinline__ void mma_tf32(float* d, u32 a0, u32 a1, u32 a2, u32 a3,
                                         u32 b0, u32 b1) {
    asm volatile(
        "mma.sync.aligned.m16n8k8.row.col.f32.tf32.tf32.f32 "
        "{%0,%1,%2,%3}, {%4,%5,%6,%7}, {%8,%9}, {%0,%1,%2,%3};"
        : "+f"(d[0]), "+f"(d[1]), "+f"(d[2]), "+f"(d[3])
        : "r"(a0), "r"(a1), "r"(a2), "r"(a3), "r"(b0), "r"(b1));
}
__device__ __forceinline__ void ffma2(u64& acc, u64 a, u64 b) {
    asm("fma.rn.f32x2 %0, %1, %2, %0;" : "+l"(acc) : "l"(a), "l"(b));
}

// ---------------------------------------------------------------------------
// Kernel P: fp32 -> tf32 bit pre-conversion (grid-stride over float4)
// ---------------------------------------------------------------------------
__global__ __launch_bounds__(256)
void cvt_kernel(const float4* __restrict__ src, uint4* __restrict__ dst, int n4)
{
    for (int i = blockIdx.x * 256 + threadIdx.x; i < n4; i += gridDim.x * 256) {
        const float4 v = src[i];
        uint4 o;
        o.x = f2tf(v.x); o.y = f2tf(v.y); o.z = f2tf(v.z); o.w = f2tf(v.w);
        dst[i] = o;
    }
}

// ===========================================================================
// tf32 MMA GEMM mainloop v2 (R14 — working): pre-converted inputs,
// coalesced LDG.128 + butterfly-shfl k-pair permute, conflict-free STS.128.
// ===========================================================================
#define TF32_GEMM_MAINLOOP(XPTR, WPTR)                                         \
    __shared__ __align__(16) u32 As[2][BM * AST];                              \
    __shared__ __align__(16) u32 Bs[2][BN * AST];                              \
    const int tid   = threadIdx.x;                                             \
    const int lane  = tid & 31;                                                \
    const int wid   = tid >> 5;                                                \
    const int m0    = blockIdx.y * BM;                                         \
    const int j0    = blockIdx.x * BN;                                         \
    const int frow  = lane >> 2;                                               \
    const int fcol  = lane & 3;                                                \
    const int wm    = wid * 32;                                                \
    const int fp    = lane >> 3;                                               \
    const int fj    = lane & 7;                                                \
    const int rbase = (fp & 1) + ((fp >> 1) << 2) + ((fj >> 2) << 1);          \
    const int qq    = (fj & 3) * 4;                                            \
    const bool oddj = (fj & 1);                                                \
    float acc[2][8][4];                                                        \
    _Pragma("unroll") for (int i = 0; i < 2; i++)                              \
        _Pragma("unroll") for (int j = 0; j < 8; j++)                          \
            _Pragma("unroll") for (int e = 0; e < 4; e++) acc[i][j][e] = 0.f;  \
    uint4 aR[4]; uint4 bR[2];                                                  \
    _Pragma("unroll") for (int s = 0; s < 4; s++) {                            \
        const int row = wm + s * 8 + rbase;                                    \
        aR[s] = *reinterpret_cast<const uint4*>(XPTR + (size_t)(m0 + row) * DIMC + qq); \
    }                                                                          \
    _Pragma("unroll") for (int s = 0; s < 2; s++) {                            \
        const int row = wid * 16 + s * 8 + rbase;                              \
        bR[s] = *reinterpret_cast<const uint4*>(WPTR + (size_t)(j0 + row) * DIMC + qq); \
    }                                                                          \
    _Pragma("unroll") for (int s = 0; s < 4; s++) {                            \
        const u32 s1 = __shfl_xor_sync(0xffffffffu, oddj ? aR[s].x : aR[s].z, 1); \
        const u32 s2 = __shfl_xor_sync(0xffffffffu, oddj ? aR[s].y : aR[s].w, 1); \
        const uint4 o = oddj ? make_uint4(s1, aR[s].z, s2, aR[s].w)            \
                             : make_uint4(aR[s].x, s1, aR[s].y, s2);           \
        const int row = wm + s * 8 + rbase;                                    \
        *reinterpret_cast<uint4*>(&As[0][row * AST + qq]) = o;                 \
    }                                                                          \
    _Pragma("unroll") for (int s = 0; s < 2; s++) {                            \
        const u32 s1 = __shfl_xor_sync(0xffffffffu, oddj ? bR[s].x : bR[s].z, 1); \
        const u32 s2 = __shfl_xor_sync(0xffffffffu, oddj ? bR[s].y : bR[s].w, 1); \
        const uint4 o = oddj ? make_uint4(s1, bR[s].z, s2, bR[s].w)            \
                             : make_uint4(bR[s].x, s1, bR[s].y, s2);           \
        const int row = wid * 16 + s * 8 + rbase;                              \
        *reinterpret_cast<uint4*>(&Bs[0][row * AST + qq]) = o;                 \
    }                                                                          \
    __syncthreads();                                                           \
    for (int t = 0; t < NCH; t++) {                                            \
        const int buf = t & 1;                                                 \
        if (t + 1 < NCH) {                                                     \
            const int kb = (t + 1) * BKC + qq;                                 \
            _Pragma("unroll") for (int s = 0; s < 4; s++) {                    \
                const int row = wm + s * 8 + rbase;                            \
                aR[s] = *reinterpret_cast<const uint4*>(XPTR + (size_t)(m0 + row) * DIMC + kb); \
            }                                                                  \
            _Pragma("unroll") for (int s = 0; s < 2; s++) {                    \
                const int row = wid * 16 + s * 8 + rbase;                      \
                bR[s] = *reinterpret_cast<const uint4*>(WPTR + (size_t)(j0 + row) * DIMC + kb); \
            }                                                                  \
        }                                                                      \
        _Pragma("unroll") for (int ks = 0; ks < 2; ks++) {                     \
            uint2 afr[2][2];                                                   \
            _Pragma("unroll") for (int am = 0; am < 2; am++) {                 \
                const int r0 = wm + am * 16 + frow;                            \
                afr[am][0] = *reinterpret_cast<const uint2*>(                  \
                    &As[buf][r0 * AST + (ks * 4 + fcol) * 2]);                 \
                afr[am][1] = *reinterpret_cast<const uint2*>(                  \
                    &As[buf][(r0 + 8) * AST + (ks * 4 + fcol) * 2]);           \
            }                                                                  \
            uint2 bfr[8];                                                      \
            _Pragma("unroll") for (int an = 0; an < 8; an++)                   \
                bfr[an] = *reinterpret_cast<const uint2*>(                     \
                    &Bs[buf][(an * 8 + frow) * AST + (ks * 4 + fcol) * 2]);    \
            _Pragma("unroll") for (int am = 0; am < 2; am++)                   \
                _Pragma("unroll") for (int an = 0; an < 8; an++)               \
                    mma_tf32(acc[am][an],                                      \
                             afr[am][0].x, afr[am][1].x,                       \
                             afr[am][0].y, afr[am][1].y,                       \
                             bfr[an].x, bfr[an].y);                            \
        }                                                                      \
        if (t + 1 < NCH) {                                                     \
            const int nb = (t + 1) & 1;                                        \
            _Pragma("unroll") for (int s = 0; s < 4; s++) {                    \
                const u32 s1 = __shfl_xor_sync(0xffffffffu, oddj ? aR[s].x : aR[s].z, 1); \
                const u32 s2 = __shfl_xor_sync(0xffffffffu, oddj ? aR[s].y : aR[s].w, 1); \
                const uint4 o = oddj ? make_uint4(s1, aR[s].z, s2, aR[s].w)    \
                                     : make_uint4(aR[s].x, s1, aR[s].y, s2);   \
                const int row = wm + s * 8 + rbase;                            \
                *reinterpret_cast<uint4*>(&As[nb][row * AST + qq]) = o;        \
            }                                                                  \
            _Pragma("unroll") for (int s = 0; s < 2; s++) {                    \
                const u32 s1 = __shfl_xor_sync(0xffffffffu, oddj ? bR[s].x : bR[s].z, 1); \
                const u32 s2 = __shfl_xor_sync(0xffffffffu, oddj ? bR[s].y : bR[s].w, 1); \
                const uint4 o = oddj ? make_uint4(s1, bR[s].z, s2, bR[s].w)    \
                                     : make_uint4(bR[s].x, s1, bR[s].y, s2);   \
                const int row = wid * 16 + s * 8 + rbase;                      \
                *reinterpret_cast<uint4*>(&Bs[nb][row * AST + qq]) = o;        \
            }                                                                  \
            __syncthreads();                                                   \
        }                                                                      \
    }

// ---------------------------------------------------------------------------
// Kernel 0: precompute bias+mask table
// ---------------------------------------------------------------------------
__global__ __launch_bounds__(256)
void bias_kernel(const float* __restrict__ mask,
                 const float* __restrict__ rpb,
                 const int*   __restrict__ rel_idx)
{
    const int wh = blockIdx.x;
    const int w  = wh / NH;
    const int h  = wh - w * NH;
    float* dst = g_bm + (size_t)wh * (NTOK * BMS);
    const float* msk = mask + (size_t)w * (NTOK * NTOK);
    for (int idx = threadIdx.x; idx < NTOK * NTOK; idx += 256) {
        const int i = idx / NTOK;
        const int j = idx - i * NTOK;
        dst[i * BMS + j] = rpb[rel_idx[idx] * NH + h] + msk[idx];
    }
}

// ---------------------------------------------------------------------------
// Kernel 1: QKV GEMM + bias, scatter into g_q/g_k/g_v [B,H,N,hd], q *= scale
// ---------------------------------------------------------------------------
__global__ __launch_bounds__(128, 3)
void qkv_gemm_kernel(const float* __restrict__ bias)
{
    const u32* Xc = g_xc;
    const u32* Wc = g_wqkv;
    TF32_GEMM_MAINLOOP(Xc, Wc)

    const int tt = j0 / DIMC;
    const int r0 = j0 - tt * DIMC;
    float* dstArr = (tt == 0) ? g_q : ((tt == 1) ? g_k : g_v);
    const float mul = (tt == 0) ? 0.17677669529663687f : 1.0f;

#pragma unroll
    for (int an = 0; an < 8; an++) {
        const int jc = an * 8 + fcol * 2;
        const float bx = bias[j0 + jc];
        const float by = bias[j0 + jc + 1];
        const int c = r0 + jc;
        const int h = c >> 5;
        const int d = c & 31;
#pragma unroll
        for (int am = 0; am < 2; am++) {
#pragma unroll
            for (int rh = 0; rh < 2; rh++) {
                const int m  = m0 + wm + am * 16 + frow + rh * 8;
                const int bi = m / NTOK;
                const int ni = m - bi * NTOK;
                const size_t dst = ((size_t)(bi * NH + h) * NTOK + ni) * HD + d;
                float2 o;
                o.x = (acc[am][an][rh * 2 + 0] + bx) * mul;
                o.y = (acc[am][an][rh * 2 + 1] + by) * mul;
                *reinterpret_cast<float2*>(&dstArr[dst]) = o;
            }
        }
    }
}

// ---------------------------------------------------------------------------
// Kernel 3: output projection  out = ctx @ proj_w.T + proj_b
// ---------------------------------------------------------------------------
__global__ __launch_bounds__(128, 3)
void proj_gemm_kernel(const float* __restrict__ bias,
                      float* __restrict__ out)
{
    const u32* Xc = g_ctx;
    const u32* Wc = g_wproj;
    TF32_GEMM_MAINLOOP(Xc, Wc)

#pragma unroll
    for (int an = 0; an < 8; an++) {
        const int jc = an * 8 + fcol * 2;
        const float bx = bias[j0 + jc];
        const float by = bias[j0 + jc + 1];
#pragma unroll
        for (int am = 0; am < 2; am++) {
#pragma unroll
            for (int rh = 0; rh < 2; rh++) {
                const int m = m0 + wm + am * 16 + frow + rh * 8;
                float2 o;
                o.x = acc[am][an][rh * 2 + 0] + bx;
                o.y = acc[am][an][rh * 2 + 1] + by;
                *reinterpret_cast<float2*>(&out[(size_t)m * DIMC + j0 + jc]) = o;
            }
        }
    }
}

// ---------------------------------------------------------------------------
// Kernel 2: per-(window, head) attention.
// R14 structure; S de-duplicated (30.2KB SMEM -> 7 blocks/SM) and softmax
// without the max pass (exp/sum only; exp(-inf)=0 handles masked entries).
// ---------------------------------------------------------------------------
#define QSTR 34
#define SST  52

__global__ __launch_bounds__(256)
void attn_kernel(float* __restrict__ attn_out)
{
    __shared__ float qs[NTOK * QSTR];
    __shared__ float ks[NTOK * QSTR];
    __shared__ float vs[NTOK * QSTR];
    __shared__ float S[NTOK * SST];

    const int bh  = blockIdx.x;
    const int b   = bh / NH;
    const int h   = bh - b * NH;
    const int tid = threadIdx.x;

    // ---- stage q/k/v as float2 ----
    const size_t base2 = (size_t)bh * (NTOK * HD / 2);
    const float2* q2 = reinterpret_cast<const float2*>(g_q) + base2;
    const float2* k2 = reinterpret_cast<const float2*>(g_k) + base2;
    const float2* v2 = reinterpret_cast<const float2*>(g_v) + base2;
    for (int idx = tid; idx < NTOK * (HD / 2); idx += 256) {
        const int r = idx >> 4, dp = idx & 15;
        *reinterpret_cast<float2*>(&qs[r * QSTR + 2 * dp]) = q2[idx];
        *reinterpret_cast<float2*>(&ks[r * QSTR + 2 * dp]) = k2[idx];
        *reinterpret_cast<float2*>(&vs[r * QSTR + 2 * dp]) = v2[idx];
    }
    __syncthreads();

    // ---- S = q k^T + bm : 4x4 register-blocked (R12 core, scalar stores) ----
    const float* bm = g_bm + (size_t)((b & (NWIN - 1)) * NH + h) * (NTOK * BMS);
    if (tid < 13 * 13) {
        const int bi = tid / 13, bj = tid - 13 * (tid / 13);
        const int i0 = bi * 4, j0 = bj * 4;
        const u64* qp[4]; const u64* kp[4];
#pragma unroll
        for (int t = 0; t < 4; t++) {
            const int ri = (i0 + t < NTOK) ? (i0 + t) : (NTOK - 1);
            const int rj = (j0 + t < NTOK) ? (j0 + t) : (NTOK - 1);
            qp[t] = reinterpret_cast<const u64*>(&qs[ri * QSTR]);
            kp[t] = reinterpret_cast<const u64*>(&ks[rj * QSTR]);
        }
        u64 acc[4][4];
#pragma unroll
        for (int a = 0; a < 4; a++)
#pragma unroll
            for (int c = 0; c < 4; c++) acc[a][c] = 0ull;
#pragma unroll
        for (int d = 0; d < HD / 2; d++) {
            u64 qv[4], kv[4];
#pragma unroll
            for (int t = 0; t < 4; t++) { qv[t] = qp[t][d]; kv[t] = kp[t][d]; }
#pragma unroll
            for (int a = 0; a < 4; a++)
#pragma unroll
                for (int c = 0; c < 4; c++)
                    ffma2(acc[a][c], qv[a], kv[c]);
        }
#pragma unroll
        for (int a = 0; a < 4; a++) {
            const int i = i0 + a;
            if (i < NTOK) {
                const float4 bmv = *reinterpret_cast<const float4*>(&bm[i * BMS + j0]);
                const float bb[4] = {bmv.x, bmv.y, bmv.z, bmv.w};
#pragma unroll
                for (int c = 0; c < 4; c++) {
                    if (j0 + c < NTOK) {
                        float2 f = *reinterpret_cast<float2*>(&acc[a][c]);
                        S[i * SST + (j0 + c)] = f.x + f.y + bb[c];
                    }
                }
            }
        }
    }
    __syncthreads();

    // ---- row softmax WITHOUT max pass (warp per row, 8 warps striding) ----
    const int lane = tid & 31;
    const int wid  = tid >> 5;
    for (int i = wid; i < NTOK; i += 8) {
        float* srow = &S[i * SST];
        const float e1 = __expf(srow[lane]);
        const float e2 = (lane < NTOK - 32) ? __expf(srow[lane + 32]) : 0.f;
        float sum = e1 + e2;
#pragma unroll
        for (int o = 16; o > 0; o >>= 1)
            sum += __shfl_xor_sync(0xffffffffu, sum, o);
        const float inv = 1.0f / sum;
        const float p1 = e1 * inv;
        const float p2 = e2 * inv;
        srow[lane] = p1;
        if (lane < NTOK - 32) srow[lane + 32] = p2;
        if (attn_out) {
            float* arow = attn_out + (size_t)bh * (NTOK * NTOK) + i * NTOK;
            arow[lane] = p1;
            if (lane < NTOK - 32) arow[lane + 32] = p2;
        }
    }
    __syncthreads();

    // ---- ctx = P V : 4 rows x 4 d-values per thread; store tf32 bits ----
    if (tid < 13 * 8) {
        const int rb = tid >> 3;
        const int dg = tid & 7;
        const int i0 = rb * 4;
        const int r1 = (i0 + 1 < NTOK) ? i0 + 1 : NTOK - 1;
        const int r2 = (i0 + 2 < NTOK) ? i0 + 2 : NTOK - 1;
        const int r3 = (i0 + 3 < NTOK) ? i0 + 3 : NTOK - 1;
        u64 c00 = 0, c01 = 0, c10 = 0, c11 = 0;
        u64 c20 = 0, c21 = 0, c30 = 0, c31 = 0;
#pragma unroll 7
        for (int j = 0; j < NTOK; j++) {
            const u64 v0 = *reinterpret_cast<const u64*>(&vs[j * QSTR + 4 * dg]);
            const u64 v1 = *reinterpret_cast<const u64*>(&vs[j * QSTR + 4 * dg + 2]);
            float2 t0; t0.x = S[i0 * SST + j]; t0.y = t0.x;
            float2 t1; t1.x = S[r1 * SST + j]; t1.y = t1.x;
            float2 t2; t2.x = S[r2 * SST + j]; t2.y = t2.x;
            float2 t3; t3.x = S[r3 * SST + j]; t3.y = t3.x;
            const u64 p0 = *reinterpret_cast<u64*>(&t0);
            const u64 p1 = *reinterpret_cast<u64*>(&t1);
            const u64 p2 = *reinterpret_cast<u64*>(&t2);
            const u64 p3 = *reinterpret_cast<u64*>(&t3);
            ffma2(c00, p0, v0); ffma2(c01, p0, v1);
            ffma2(c10, p1, v0); ffma2(c11, p1, v1);
            ffma2(c20, p2, v0); ffma2(c21, p2, v1);
            ffma2(c30, p3, v0); ffma2(c31, p3, v1);
        }
        const size_t ob = (size_t)b * NTOK * DIMC + h * HD + 4 * dg;
        u64 cc[4][2] = {{c00, c01}, {c10, c11}, {c20, c21}, {c30, c31}};
#pragma unroll
        for (int r = 0; r < 4; r++) {
            if (i0 + r < NTOK) {
                float2 lo = *reinterpret_cast<float2*>(&cc[r][0]);
                float2 hi = *reinterpret_cast<float2*>(&cc[r][1]);
                uint4 o;
                o.x = f2tf(lo.x); o.y = f2tf(lo.y);
                o.z = f2tf(hi.x); o.w = f2tf(hi.y);
                *reinterpret_cast<uint4*>(&g_ctx[ob + (size_t)(i0 + r) * DIMC]) = o;
            }
        }
    }
}

// ---------------------------------------------------------------------------
// Launch
// ---------------------------------------------------------------------------
extern "C" void kernel_launch(void* const* d_in, const int* in_sizes, int n_in,
                              void* d_out, int out_size)
{
    const float* x      = (const float*)d_in[0];
    const float* mask   = (const float*)d_in[1];
    const float* qkv_w  = (const float*)d_in[2];
    const float* qkv_b  = (const float*)d_in[3];
    const float* proj_w = (const float*)d_in[4];
    const float* proj_b = (const float*)d_in[5];
    const float* rpb    = (const float*)d_in[6];
    const int*   relidx = (const int*)d_in[7];

    float* out = (float*)d_out;
    const long OUT_ELEMS  = (long)B_ * NTOK * DIMC;          // 38,535,168
    const long ATTN_ELEMS = (long)B_ * NH * NTOK * NTOK;     // 59,006,976
    float* attn_out = nullptr;
    if ((long)out_size >= OUT_ELEMS + ATTN_ELEMS) attn_out = out + OUT_ELEMS;

    u32* d_xc;    cudaGetSymbolAddress((void**)&d_xc,    g_xc);
    u32* d_wqkv;  cudaGetSymbolAddress((void**)&d_wqkv,  g_wqkv);
    u32* d_wproj; cudaGetSymbolAddress((void**)&d_wproj, g_wproj);

    cvt_kernel<<<4096, 256>>>((const float4*)x, (uint4*)d_xc,
                              (int)(OUT_ELEMS / 4));
    cvt_kernel<<<108, 256>>>((const float4*)qkv_w, (uint4*)d_wqkv,
                             (3 * DIMC * DIMC) / 4);
    cvt_kernel<<<36, 256>>>((const float4*)proj_w, (uint4*)d_wproj,
                            (DIMC * DIMC) / 4);

    bias_kernel<<<NWIN * NH, 256>>>(mask, rpb, relidx);
    qkv_gemm_kernel<<<dim3(576 / BN, (B_ * NTOK) / BM), 128>>>(qkv_b);
    attn_kernel<<<B_ * NH, 256>>>(attn_out);
    proj_gemm_kernel<<<dim3(DIMC / BN, (B_ * NTOK) / BM), 128>>>(proj_b, out);

    (void)in_sizes; (void)n_in;
}

// round 16
// speedup vs baseline: 1.2110x; 1.0001x over previous
#include <cuda_runtime.h>

#define B_    4096
#define NTOK  49
#define DIMC  192
#define NH    6
#define HD    32
#define NWIN  64

#define BM  128
#define BN  64
#define BKC 16
#define NCH (DIMC / BKC)   // 12 k-chunks
#define AST 24             // u32 stride per SMEM row (conflict-free fragments)

typedef unsigned long long u64;
typedef unsigned int u32;

// Scratch (device globals — allocation-free per harness rules)
__device__ float g_q[(size_t)B_ * NH * NTOK * HD];   // q pre-scaled by hd^-0.5
__device__ float g_k[(size_t)B_ * NH * NTOK * HD];
__device__ float g_v[(size_t)B_ * NH * NTOK * HD];
__device__ u32   g_ctx[(size_t)B_ * NTOK * DIMC];    // attention output, tf32 bits
__device__ u32   g_xc[(size_t)B_ * NTOK * DIMC];     // x pre-converted to tf32
__device__ u32   g_wqkv[3 * DIMC * DIMC];            // qkv_w tf32
__device__ u32   g_wproj[DIMC * DIMC];               // proj_w tf32

#define BMS 52
__device__ float g_bm[(size_t)NWIN * NH * NTOK * BMS];  // rpb-gather + mask

__device__ __forceinline__ u32 f2tf(float f) {
    u32 r; asm("cvt.rna.tf32.f32 %0, %1;" : "=r"(r) : "f"(f)); return r;
}
__device__ __forceinline__ void mma_tf32(float* d, u32 a0, u32 a1, u32 a2, u32 a3,
                                         u32 b0, u32 b1) {
    asm volatile(
        "mma.sync.aligned.m16n8k8.row.col.f32.tf32.tf32.f32 "
        "{%0,%1,%2,%3}, {%4,%5,%6,%7}, {%8,%9}, {%0,%1,%2,%3};"
        : "+f"(d[0]), "+f"(d[1]), "+f"(d[2]), "+f"(d[3])
        : "r"(a0), "r"(a1), "r"(a2), "r"(a3), "r"(b0), "r"(b1));
}
__device__ __forceinline__ void ffma2(u64& acc, u64 a, u64 b) {
    asm("fma.rn.f32x2 %0, %1, %2, %0;" : "+l"(acc) : "l"(a), "l"(b));
}

// ---------------------------------------------------------------------------
// Kernel P: fp32 -> tf32 bit pre-conversion (grid-stride over float4)
// ---------------------------------------------------------------------------
__global__ __launch_bounds__(256)
void cvt_kernel(const float4* __restrict__ src, uint4* __restrict__ dst, int n4)
{
    for (int i = blockIdx.x * 256 + threadIdx.x; i < n4; i += gridDim.x * 256) {
        const float4 v = src[i];
        uint4 o;
        o.x = f2tf(v.x); o.y = f2tf(v.y); o.z = f2tf(v.z); o.w = f2tf(v.w);
        dst[i] = o;
    }
}

// ===========================================================================
// tf32 MMA GEMM mainloop v2 (R14/R15 — working): pre-converted inputs,
// coalesced LDG.128 + butterfly-shfl k-pair permute, conflict-free STS.128.
// ===========================================================================
#define TF32_GEMM_MAINLOOP(XPTR, WPTR)                                         \
    __shared__ __align__(16) u32 As[2][BM * AST];                              \
    __shared__ __align__(16) u32 Bs[2][BN * AST];                              \
    const int tid   = threadIdx.x;                                             \
    const int lane  = tid & 31;                                                \
    const int wid   = tid >> 5;                                                \
    const int m0    = blockIdx.y * BM;                                         \
    const int j0    = blockIdx.x * BN;                                         \
    const int frow  = lane >> 2;                                               \
    const int fcol  = lane & 3;                                                \
    const int wm    = wid * 32;                                                \
    const int fp    = lane >> 3;                                               \
    const int fj    = lane & 7;                                                \
    const int rbase = (fp & 1) + ((fp >> 1) << 2) + ((fj >> 2) << 1);          \
    const int qq    = (fj & 3) * 4;                                            \
    const bool oddj = (fj & 1);                                                \
    float acc[2][8][4];                                                        \
    _Pragma("unroll") for (int i = 0; i < 2; i++)                              \
        _Pragma("unroll") for (int j = 0; j < 8; j++)                          \
            _Pragma("unroll") for (int e = 0; e < 4; e++) acc[i][j][e] = 0.f;  \
    uint4 aR[4]; uint4 bR[2];                                                  \
    _Pragma("unroll") for (int s = 0; s < 4; s++) {                            \
        const int row = wm + s * 8 + rbase;                                    \
        aR[s] = *reinterpret_cast<const uint4*>(XPTR + (size_t)(m0 + row) * DIMC + qq); \
    }                                                                          \
    _Pragma("unroll") for (int s = 0; s < 2; s++) {                            \
        const int row = wid * 16 + s * 8 + rbase;                              \
        bR[s] = *reinterpret_cast<const uint4*>(WPTR + (size_t)(j0 + row) * DIMC + qq); \
    }                                                                          \
    _Pragma("unroll") for (int s = 0; s < 4; s++) {                            \
        const u32 s1 = __shfl_xor_sync(0xffffffffu, oddj ? aR[s].x : aR[s].z, 1); \
        const u32 s2 = __shfl_xor_sync(0xffffffffu, oddj ? aR[s].y : aR[s].w, 1); \
        const uint4 o = oddj ? make_uint4(s1, aR[s].z, s2, aR[s].w)            \
                             : make_uint4(aR[s].x, s1, aR[s].y, s2);           \
        const int row = wm + s * 8 + rbase;                                    \
        *reinterpret_cast<uint4*>(&As[0][row * AST + qq]) = o;                 \
    }                                                                          \
    _Pragma("unroll") for (int s = 0; s < 2; s++) {                            \
        const u32 s1 = __shfl_xor_sync(0xffffffffu, oddj ? bR[s].x : bR[s].z, 1); \
        const u32 s2 = __shfl_xor_sync(0xffffffffu, oddj ? bR[s].y : bR[s].w, 1); \
        const uint4 o = oddj ? make_uint4(s1, bR[s].z, s2, bR[s].w)            \
                             : make_uint4(bR[s].x, s1, bR[s].y, s2);           \
        const int row = wid * 16 + s * 8 + rbase;                              \
        *reinterpret_cast<uint4*>(&Bs[0][row * AST + qq]) = o;                 \
    }                                                                          \
    __syncthreads();                                                           \
    for (int t = 0; t < NCH; t++) {                                            \
        const int buf = t & 1;                                                 \
        if (t + 1 < NCH) {                                                     \
            const int kb = (t + 1) * BKC + qq;                                 \
            _Pragma("unroll") for (int s = 0; s < 4; s++) {                    \
                const int row = wm + s * 8 + rbase;                            \
                aR[s] = *reinterpret_cast<const uint4*>(XPTR + (size_t)(m0 + row) * DIMC + kb); \
            }                                                                  \
            _Pragma("unroll") for (int s = 0; s < 2; s++) {                    \
                const int row = wid * 16 + s * 8 + rbase;                      \
                bR[s] = *reinterpret_cast<const uint4*>(WPTR + (size_t)(j0 + row) * DIMC + kb); \
            }                                                                  \
        }                                                                      \
        _Pragma("unroll") for (int ks = 0; ks < 2; ks++) {                     \
            uint2 afr[2][2];                                                   \
            _Pragma("unroll") for (int am = 0; am < 2; am++) {                 \
                const int r0 = wm + am * 16 + frow;                            \
                afr[am][0] = *reinterpret_cast<const uint2*>(                  \
                    &As[buf][r0 * AST + (ks * 4 + fcol) * 2]);                 \
                afr[am][1] = *reinterpret_cast<const uint2*>(                  \
                    &As[buf][(r0 + 8) * AST + (ks * 4 + fcol) * 2]);           \
            }                                                                  \
            uint2 bfr[8];                                                      \
            _Pragma("unroll") for (int an = 0; an < 8; an++)                   \
                bfr[an] = *reinterpret_cast<const uint2*>(                     \
                    &Bs[buf][(an * 8 + frow) * AST + (ks * 4 + fcol) * 2]);    \
            _Pragma("unroll") for (int am = 0; am < 2; am++)                   \
                _Pragma("unroll") for (int an = 0; an < 8; an++)               \
                    mma_tf32(acc[am][an],                                      \
                             afr[am][0].x, afr[am][1].x,                       \
                             afr[am][0].y, afr[am][1].y,                       \
                             bfr[an].x, bfr[an].y);                            \
        }                                                                      \
        if (t + 1 < NCH) {                                                     \
            const int nb = (t + 1) & 1;                                        \
            _Pragma("unroll") for (int s = 0; s < 4; s++) {                    \
                const u32 s1 = __shfl_xor_sync(0xffffffffu, oddj ? aR[s].x : aR[s].z, 1); \
                const u32 s2 = __shfl_xor_sync(0xffffffffu, oddj ? aR[s].y : aR[s].w, 1); \
                const uint4 o = oddj ? make_uint4(s1, aR[s].z, s2, aR[s].w)    \
                                     : make_uint4(aR[s].x, s1, aR[s].y, s2);   \
                const int row = wm + s * 8 + rbase;                            \
                *reinterpret_cast<uint4*>(&As[nb][row * AST + qq]) = o;        \
            }                                                                  \
            _Pragma("unroll") for (int s = 0; s < 2; s++) {                    \
                const u32 s1 = __shfl_xor_sync(0xffffffffu, oddj ? bR[s].x : bR[s].z, 1); \
                const u32 s2 = __shfl_xor_sync(0xffffffffu, oddj ? bR[s].y : bR[s].w, 1); \
                const uint4 o = oddj ? make_uint4(s1, bR[s].z, s2, bR[s].w)    \
                                     : make_uint4(bR[s].x, s1, bR[s].y, s2);   \
                const int row = wid * 16 + s * 8 + rbase;                      \
                *reinterpret_cast<uint4*>(&Bs[nb][row * AST + qq]) = o;        \
            }                                                                  \
            __syncthreads();                                                   \
        }                                                                      \
    }

// ---------------------------------------------------------------------------
// Kernel 0: precompute bias+mask table
// ---------------------------------------------------------------------------
__global__ __launch_bounds__(256)
void bias_kernel(const float* __restrict__ mask,
                 const float* __restrict__ rpb,
                 const int*   __restrict__ rel_idx)
{
    const int wh = blockIdx.x;
    const int w  = wh / NH;
    const int h  = wh - w * NH;
    float* dst = g_bm + (size_t)wh * (NTOK * BMS);
    const float* msk = mask + (size_t)w * (NTOK * NTOK);
    for (int idx = threadIdx.x; idx < NTOK * NTOK; idx += 256) {
        const int i = idx / NTOK;
        const int j = idx - i * NTOK;
        dst[i * BMS + j] = rpb[rel_idx[idx] * NH + h] + msk[idx];
    }
}

// ---------------------------------------------------------------------------
// Kernel 1: QKV GEMM + bias, scatter into g_q/g_k/g_v [B,H,N,hd], q *= scale
// R16: __launch_bounds__(128, 4) -> regs<=128 -> 4 CTAs/SM
// ---------------------------------------------------------------------------
__global__ __launch_bounds__(128, 4)
void qkv_gemm_kernel(const float* __restrict__ bias)
{
    const u32* Xc = g_xc;
    const u32* Wc = g_wqkv;
    TF32_GEMM_MAINLOOP(Xc, Wc)

    const int tt = j0 / DIMC;
    const int r0 = j0 - tt * DIMC;
    float* dstArr = (tt == 0) ? g_q : ((tt == 1) ? g_k : g_v);
    const float mul = (tt == 0) ? 0.17677669529663687f : 1.0f;

#pragma unroll
    for (int an = 0; an < 8; an++) {
        const int jc = an * 8 + fcol * 2;
        const float bx = bias[j0 + jc];
        const float by = bias[j0 + jc + 1];
        const int c = r0 + jc;
        const int h = c >> 5;
        const int d = c & 31;
#pragma unroll
        for (int am = 0; am < 2; am++) {
#pragma unroll
            for (int rh = 0; rh < 2; rh++) {
                const int m  = m0 + wm + am * 16 + frow + rh * 8;
                const int bi = m / NTOK;
                const int ni = m - bi * NTOK;
                const size_t dst = ((size_t)(bi * NH + h) * NTOK + ni) * HD + d;
                float2 o;
                o.x = (acc[am][an][rh * 2 + 0] + bx) * mul;
                o.y = (acc[am][an][rh * 2 + 1] + by) * mul;
                *reinterpret_cast<float2*>(&dstArr[dst]) = o;
            }
        }
    }
}

// ---------------------------------------------------------------------------
// Kernel 3: output projection  out = ctx @ proj_w.T + proj_b
// ---------------------------------------------------------------------------
__global__ __launch_bounds__(128, 4)
void proj_gemm_kernel(const float* __restrict__ bias,
                      float* __restrict__ out)
{
    const u32* Xc = g_ctx;
    const u32* Wc = g_wproj;
    TF32_GEMM_MAINLOOP(Xc, Wc)

#pragma unroll
    for (int an = 0; an < 8; an++) {
        const int jc = an * 8 + fcol * 2;
        const float bx = bias[j0 + jc];
        const float by = bias[j0 + jc + 1];
#pragma unroll
        for (int am = 0; am < 2; am++) {
#pragma unroll
            for (int rh = 0; rh < 2; rh++) {
                const int m = m0 + wm + am * 16 + frow + rh * 8;
                float2 o;
                o.x = acc[am][an][rh * 2 + 0] + bx;
                o.y = acc[am][an][rh * 2 + 1] + by;
                *reinterpret_cast<float2*>(&out[(size_t)m * DIMC + j0 + jc]) = o;
            }
        }
    }
}

// ---------------------------------------------------------------------------
// Kernel 2: per-(window, head) attention (R15 — at its MUFU floor; frozen).
// ---------------------------------------------------------------------------
#define QSTR 34
#define SST  52

__global__ __launch_bounds__(256)
void attn_kernel(float* __restrict__ attn_out)
{
    __shared__ float qs[NTOK * QSTR];
    __shared__ float ks[NTOK * QSTR];
    __shared__ float vs[NTOK * QSTR];
    __shared__ float S[NTOK * SST];

    const int bh  = blockIdx.x;
    const int b   = bh / NH;
    const int h   = bh - b * NH;
    const int tid = threadIdx.x;

    const size_t base2 = (size_t)bh * (NTOK * HD / 2);
    const float2* q2 = reinterpret_cast<const float2*>(g_q) + base2;
    const float2* k2 = reinterpret_cast<const float2*>(g_k) + base2;
    const float2* v2 = reinterpret_cast<const float2*>(g_v) + base2;
    for (int idx = tid; idx < NTOK * (HD / 2); idx += 256) {
        const int r = idx >> 4, dp = idx & 15;
        *reinterpret_cast<float2*>(&qs[r * QSTR + 2 * dp]) = q2[idx];
        *reinterpret_cast<float2*>(&ks[r * QSTR + 2 * dp]) = k2[idx];
        *reinterpret_cast<float2*>(&vs[r * QSTR + 2 * dp]) = v2[idx];
    }
    __syncthreads();

    const float* bm = g_bm + (size_t)((b & (NWIN - 1)) * NH + h) * (NTOK * BMS);
    if (tid < 13 * 13) {
        const int bi = tid / 13, bj = tid - 13 * (tid / 13);
        const int i0 = bi * 4, j0 = bj * 4;
        const u64* qp[4]; const u64* kp[4];
#pragma unroll
        for (int t = 0; t < 4; t++) {
            const int ri = (i0 + t < NTOK) ? (i0 + t) : (NTOK - 1);
            const int rj = (j0 + t < NTOK) ? (j0 + t) : (NTOK - 1);
            qp[t] = reinterpret_cast<const u64*>(&qs[ri * QSTR]);
            kp[t] = reinterpret_cast<const u64*>(&ks[rj * QSTR]);
        }
        u64 acc[4][4];
#pragma unroll
        for (int a = 0; a < 4; a++)
#pragma unroll
            for (int c = 0; c < 4; c++) acc[a][c] = 0ull;
#pragma unroll
        for (int d = 0; d < HD / 2; d++) {
            u64 qv[4], kv[4];
#pragma unroll
            for (int t = 0; t < 4; t++) { qv[t] = qp[t][d]; kv[t] = kp[t][d]; }
#pragma unroll
            for (int a = 0; a < 4; a++)
#pragma unroll
                for (int c = 0; c < 4; c++)
                    ffma2(acc[a][c], qv[a], kv[c]);
        }
#pragma unroll
        for (int a = 0; a < 4; a++) {
            const int i = i0 + a;
            if (i < NTOK) {
                const float4 bmv = *reinterpret_cast<const float4*>(&bm[i * BMS + j0]);
                const float bb[4] = {bmv.x, bmv.y, bmv.z, bmv.w};
#pragma unroll
                for (int c = 0; c < 4; c++) {
                    if (j0 + c < NTOK) {
                        float2 f = *reinterpret_cast<float2*>(&acc[a][c]);
                        S[i * SST + (j0 + c)] = f.x + f.y + bb[c];
                    }
                }
            }
        }
    }
    __syncthreads();

    const int lane = tid & 31;
    const int wid  = tid >> 5;
    for (int i = wid; i < NTOK; i += 8) {
        float* srow = &S[i * SST];
        const float e1 = __expf(srow[lane]);
        const float e2 = (lane < NTOK - 32) ? __expf(srow[lane + 32]) : 0.f;
        float sum = e1 + e2;
#pragma unroll
        for (int o = 16; o > 0; o >>= 1)
            sum += __shfl_xor_sync(0xffffffffu, sum, o);
        const float inv = 1.0f / sum;
        const float p1 = e1 * inv;
        const float p2 = e2 * inv;
        srow[lane] = p1;
        if (lane < NTOK - 32) srow[lane + 32] = p2;
        if (attn_out) {
            float* arow = attn_out + (size_t)bh * (NTOK * NTOK) + i * NTOK;
            arow[lane] = p1;
            if (lane < NTOK - 32) arow[lane + 32] = p2;
        }
    }
    __syncthreads();

    if (tid < 13 * 8) {
        const int rb = tid >> 3;
        const int dg = tid & 7;
        const int i0 = rb * 4;
        const int r1 = (i0 + 1 < NTOK) ? i0 + 1 : NTOK - 1;
        const int r2 = (i0 + 2 < NTOK) ? i0 + 2 : NTOK - 1;
        const int r3 = (i0 + 3 < NTOK) ? i0 + 3 : NTOK - 1;
        u64 c00 = 0, c01 = 0, c10 = 0, c11 = 0;
        u64 c20 = 0, c21 = 0, c30 = 0, c31 = 0;
#pragma unroll 7
        for (int j = 0; j < NTOK; j++) {
            const u64 v0 = *reinterpret_cast<const u64*>(&vs[j * QSTR + 4 * dg]);
            const u64 v1 = *reinterpret_cast<const u64*>(&vs[j * QSTR + 4 * dg + 2]);
            float2 t0; t0.x = S[i0 * SST + j]; t0.y = t0.x;
            float2 t1; t1.x = S[r1 * SST + j]; t1.y = t1.x;
            float2 t2; t2.x = S[r2 * SST + j]; t2.y = t2.x;
            float2 t3; t3.x = S[r3 * SST + j]; t3.y = t3.x;
            const u64 p0 = *reinterpret_cast<u64*>(&t0);
            const u64 p1 = *reinterpret_cast<u64*>(&t1);
            const u64 p2 = *reinterpret_cast<u64*>(&t2);
            const u64 p3 = *reinterpret_cast<u64*>(&t3);
            ffma2(c00, p0, v0); ffma2(c01, p0, v1);
            ffma2(c10, p1, v0); ffma2(c11, p1, v1);
            ffma2(c20, p2, v0); ffma2(c21, p2, v1);
            ffma2(c30, p3, v0); ffma2(c31, p3, v1);
        }
        const size_t ob = (size_t)b * NTOK * DIMC + h * HD + 4 * dg;
        u64 cc[4][2] = {{c00, c01}, {c10, c11}, {c20, c21}, {c30, c31}};
#pragma unroll
        for (int r = 0; r < 4; r++) {
            if (i0 + r < NTOK) {
                float2 lo = *reinterpret_cast<float2*>(&cc[r][0]);
                float2 hi = *reinterpret_cast<float2*>(&cc[r][1]);
                uint4 o;
                o.x = f2tf(lo.x); o.y = f2tf(lo.y);
                o.z = f2tf(hi.x); o.w = f2tf(hi.y);
                *reinterpret_cast<uint4*>(&g_ctx[ob + (size_t)(i0 + r) * DIMC]) = o;
            }
        }
    }
}

// ---------------------------------------------------------------------------
// Launch
// ---------------------------------------------------------------------------
extern "C" void kernel_launch(void* const* d_in, const int* in_sizes, int n_in,
                              void* d_out, int out_size)
{
    const float* x      = (const float*)d_in[0];
    const float* mask   = (const float*)d_in[1];
    const float* qkv_w  = (const float*)d_in[2];
    const float* qkv_b  = (const float*)d_in[3];
    const float* proj_w = (const float*)d_in[4];
    const float* proj_b = (const float*)d_in[5];
    const float* rpb    = (const float*)d_in[6];
    const int*   relidx = (const int*)d_in[7];

    float* out = (float*)d_out;
    const long OUT_ELEMS  = (long)B_ * NTOK * DIMC;          // 38,535,168
    const long ATTN_ELEMS = (long)B_ * NH * NTOK * NTOK;     // 59,006,976
    float* attn_out = nullptr;
    if ((long)out_size >= OUT_ELEMS + ATTN_ELEMS) attn_out = out + OUT_ELEMS;

    u32* d_xc;    cudaGetSymbolAddress((void**)&d_xc,    g_xc);
    u32* d_wqkv;  cudaGetSymbolAddress((void**)&d_wqkv,  g_wqkv);
    u32* d_wproj; cudaGetSymbolAddress((void**)&d_wproj, g_wproj);

    cvt_kernel<<<4096, 256>>>((const float4*)x, (uint4*)d_xc,
                              (int)(OUT_ELEMS / 4));
    cvt_kernel<<<108, 256>>>((const float4*)qkv_w, (uint4*)d_wqkv,
                             (3 * DIMC * DIMC) / 4);
    cvt_kernel<<<36, 256>>>((const float4*)proj_w, (uint4*)d_wproj,
                            (DIMC * DIMC) / 4);

    bias_kernel<<<NWIN * NH, 256>>>(mask, rpb, relidx);
    qkv_gemm_kernel<<<dim3(576 / BN, (B_ * NTOK) / BM), 128>>>(qkv_b);
    attn_kernel<<<B_ * NH, 256>>>(attn_out);
    proj_gemm_kernel<<<dim3(DIMC / BN, (B_ * NTOK) / BM), 128>>>(proj_b, out);

    (void)in_sizes; (void)n_in;
}

// round 17
// speedup vs baseline: 1.3855x; 1.1441x over previous
#include <cuda_runtime.h>

#define B_    4096
#define NTOK  49
#define DIMC  192
#define NH    6
#define HD    32
#define NWIN  64

#define BM  128
#define BN  64
#define BKC 16
#define NCH (DIMC / BKC)   // 12 k-chunks
#define AST 20             // u32 row stride: conflict-free LDSM (r*20 mod 32 covers all quads)

typedef unsigned long long u64;
typedef unsigned int u32;

// Scratch (device globals — allocation-free per harness rules)
__device__ float g_q[(size_t)B_ * NH * NTOK * HD];   // q pre-scaled by hd^-0.5
__device__ float g_k[(size_t)B_ * NH * NTOK * HD];
__device__ float g_v[(size_t)B_ * NH * NTOK * HD];
__device__ u32   g_ctx[(size_t)B_ * NTOK * DIMC];    // attention output, tf32 bits
__device__ u32   g_xc[(size_t)B_ * NTOK * DIMC];     // x pre-converted to tf32
__device__ u32   g_wqkv[3 * DIMC * DIMC];            // qkv_w tf32
__device__ u32   g_wproj[DIMC * DIMC];               // proj_w tf32

#define BMS 52
__device__ float g_bm[(size_t)NWIN * NH * NTOK * BMS];  // rpb-gather + mask

__device__ __forceinline__ u32 f2tf(float f) {
    u32 r; asm("cvt.rna.tf32.f32 %0, %1;" : "=r"(r) : "f"(f)); return r;
}
__device__ __forceinline__ void mma_tf32(float* d, u32 a0, u32 a1, u32 a2, u32 a3,
                                         u32 b0, u32 b1) {
    asm volatile(
        "mma.sync.aligned.m16n8k8.row.col.f32.tf32.tf32.f32 "
        "{%0,%1,%2,%3}, {%4,%5,%6,%7}, {%8,%9}, {%0,%1,%2,%3};"
        : "+f"(d[0]), "+f"(d[1]), "+f"(d[2]), "+f"(d[3])
        : "r"(a0), "r"(a1), "r"(a2), "r"(a3), "r"(b0), "r"(b1));
}
__device__ __forceinline__ void ffma2(u64& acc, u64 a, u64 b) {
    asm("fma.rn.f32x2 %0, %1, %2, %0;" : "+l"(acc) : "l"(a), "l"(b));
}
__device__ __forceinline__ u32 smem_u32(const void* p) {
    return (u32)__cvta_generic_to_shared(p);
}
__device__ __forceinline__ void cp_async16(u32 dst, const u32* src) {
    asm volatile("cp.async.cg.shared.global [%0], [%1], 16;" :: "r"(dst), "l"(src));
}
#define CP_COMMIT asm volatile("cp.async.commit_group;")
#define CP_WAIT1  asm volatile("cp.async.wait_group 1;")
__device__ __forceinline__ void ldsm_x4(u32& r0, u32& r1, u32& r2, u32& r3, u32 addr) {
    asm volatile("ldmatrix.sync.aligned.m8n8.x4.shared.b16 {%0,%1,%2,%3}, [%4];"
                 : "=r"(r0), "=r"(r1), "=r"(r2), "=r"(r3) : "r"(addr));
}

// ---------------------------------------------------------------------------
// Kernel P: fp32 -> tf32 bit pre-conversion (grid-stride over float4)
// ---------------------------------------------------------------------------
__global__ __launch_bounds__(256)
void cvt_kernel(const float4* __restrict__ src, uint4* __restrict__ dst, int n4)
{
    for (int i = blockIdx.x * 256 + threadIdx.x; i < n4; i += gridDim.x * 256) {
        const float4 v = src[i];
        uint4 o;
        o.x = f2tf(v.x); o.y = f2tf(v.y); o.z = f2tf(v.z); o.w = f2tf(v.w);
        dst[i] = o;
    }
}

// ===========================================================================
// tf32 MMA GEMM mainloop v3: cp.async 3-stage pipeline + ldmatrix fragments.
// Plain row layout (AST=20 u32): LDSM rows hit all 32 banks (conflict-free).
// Accumulator layout identical to v2 -> epilogues unchanged.
// ===========================================================================
#define GEMM_ISSUE(st, kb, XPTR, WPTR)                                         \
    do {                                                                       \
        _Pragma("unroll") for (int s = 0; s < 4; s++) {                        \
            const int row = s * 32 + crow;                                     \
            cp_async16(as0 + (u32)((((st) * BM + row) * AST + ccg * 4) * 4),   \
                       XPTR + (size_t)(m0 + row) * DIMC + (kb) + ccg * 4);     \
        }                                                                      \
        _Pragma("unroll") for (int s = 0; s < 2; s++) {                        \
            const int row = s * 32 + crow;                                     \
            cp_async16(bs0 + (u32)((((st) * BN + row) * AST + ccg * 4) * 4),   \
                       WPTR + (size_t)(j0 + row) * DIMC + (kb) + ccg * 4);     \
        }                                                                      \
    } while (0)

#define TF32_GEMM_MAINLOOP(XPTR, WPTR)                                         \
    __shared__ __align__(16) u32 As[3][BM * AST];                              \
    __shared__ __align__(16) u32 Bs[3][BN * AST];                              \
    const int tid   = threadIdx.x;                                             \
    const int lane  = tid & 31;                                                \
    const int wid   = tid >> 5;                                                \
    const int m0    = blockIdx.y * BM;                                         \
    const int j0    = blockIdx.x * BN;                                         \
    const int frow  = lane >> 2;                                               \
    const int fcol  = lane & 3;                                                \
    const int wm    = wid * 32;                                                \
    const int crow  = tid >> 2;                                                \
    const int ccg   = tid & 3;                                                 \
    const u32 as0   = smem_u32(As);                                            \
    const u32 bs0   = smem_u32(Bs);                                            \
    /* LDSM per-lane byte offsets (stage-relative, ks=0, tile 0) */            \
    const u32 aoff = (u32)(((wm + (lane & 7) + ((lane >> 3) & 1) * 8) * AST    \
                            + ((lane >> 4) & 1) * 4) * 4);                     \
    const u32 boff = (u32)(((((lane >> 4) & 1) * 8 + (lane & 7)) * AST         \
                            + ((lane >> 3) & 1) * 4) * 4);                     \
    float acc[2][8][4];                                                        \
    _Pragma("unroll") for (int i = 0; i < 2; i++)                              \
        _Pragma("unroll") for (int j = 0; j < 8; j++)                          \
            _Pragma("unroll") for (int e = 0; e < 4; e++) acc[i][j][e] = 0.f;  \
    GEMM_ISSUE(0, 0, XPTR, WPTR); CP_COMMIT;                                   \
    GEMM_ISSUE(1, BKC, XPTR, WPTR); CP_COMMIT;                                 \
    for (int t = 0; t < NCH; t++) {                                            \
        CP_WAIT1;                                                              \
        __syncthreads();                                                       \
        if (t + 2 < NCH) { GEMM_ISSUE((t + 2) % 3, (t + 2) * BKC, XPTR, WPTR); } \
        CP_COMMIT;                                                             \
        const u32 a_st = as0 + (u32)(((t % 3) * BM * AST) * 4);                \
        const u32 b_st = bs0 + (u32)(((t % 3) * BN * AST) * 4);                \
        _Pragma("unroll") for (int ks = 0; ks < 2; ks++) {                     \
            u32 af[2][4];                                                      \
            _Pragma("unroll") for (int am = 0; am < 2; am++)                   \
                ldsm_x4(af[am][0], af[am][1], af[am][2], af[am][3],            \
                        a_st + aoff + (u32)(am * 16 * AST * 4 + ks * 32));     \
            u32 bf[4][4];                                                      \
            _Pragma("unroll") for (int p = 0; p < 4; p++)                      \
                ldsm_x4(bf[p][0], bf[p][1], bf[p][2], bf[p][3],                \
                        b_st + boff + (u32)(p * 16 * AST * 4 + ks * 32));      \
            _Pragma("unroll") for (int am = 0; am < 2; am++)                   \
                _Pragma("unroll") for (int an = 0; an < 8; an++) {             \
                    const int p = an >> 1, hc = an & 1;                        \
                    mma_tf32(acc[am][an], af[am][0], af[am][1],                \
                             af[am][2], af[am][3],                             \
                             bf[p][hc * 2], bf[p][hc * 2 + 1]);                \
                }                                                              \
        }                                                                      \
    }

// ---------------------------------------------------------------------------
// Kernel 0: precompute bias+mask table
// ---------------------------------------------------------------------------
__global__ __launch_bounds__(256)
void bias_kernel(const float* __restrict__ mask,
                 const float* __restrict__ rpb,
                 const int*   __restrict__ rel_idx)
{
    const int wh = blockIdx.x;
    const int w  = wh / NH;
    const int h  = wh - w * NH;
    float* dst = g_bm + (size_t)wh * (NTOK * BMS);
    const float* msk = mask + (size_t)w * (NTOK * NTOK);
    for (int idx = threadIdx.x; idx < NTOK * NTOK; idx += 256) {
        const int i = idx / NTOK;
        const int j = idx - i * NTOK;
        dst[i * BMS + j] = rpb[rel_idx[idx] * NH + h] + msk[idx];
    }
}

// ---------------------------------------------------------------------------
// Kernel 1: QKV GEMM + bias, scatter into g_q/g_k/g_v [B,H,N,hd], q *= scale
// ---------------------------------------------------------------------------
__global__ __launch_bounds__(128, 4)
void qkv_gemm_kernel(const float* __restrict__ bias)
{
    const u32* Xc = g_xc;
    const u32* Wc = g_wqkv;
    TF32_GEMM_MAINLOOP(Xc, Wc)

    const int tt = j0 / DIMC;
    const int r0 = j0 - tt * DIMC;
    float* dstArr = (tt == 0) ? g_q : ((tt == 1) ? g_k : g_v);
    const float mul = (tt == 0) ? 0.17677669529663687f : 1.0f;

#pragma unroll
    for (int an = 0; an < 8; an++) {
        const int jc = an * 8 + fcol * 2;
        const float bx = bias[j0 + jc];
        const float by = bias[j0 + jc + 1];
        const int c = r0 + jc;
        const int h = c >> 5;
        const int d = c & 31;
#pragma unroll
        for (int am = 0; am < 2; am++) {
#pragma unroll
            for (int rh = 0; rh < 2; rh++) {
                const int m  = m0 + wm + am * 16 + frow + rh * 8;
                const int bi = m / NTOK;
                const int ni = m - bi * NTOK;
                const size_t dst = ((size_t)(bi * NH + h) * NTOK + ni) * HD + d;
                float2 o;
                o.x = (acc[am][an][rh * 2 + 0] + bx) * mul;
                o.y = (acc[am][an][rh * 2 + 1] + by) * mul;
                *reinterpret_cast<float2*>(&dstArr[dst]) = o;
            }
        }
    }
}

// ---------------------------------------------------------------------------
// Kernel 3: output projection  out = ctx @ proj_w.T + proj_b
// ---------------------------------------------------------------------------
__global__ __launch_bounds__(128, 4)
void proj_gemm_kernel(const float* __restrict__ bias,
                      float* __restrict__ out)
{
    const u32* Xc = g_ctx;
    const u32* Wc = g_wproj;
    TF32_GEMM_MAINLOOP(Xc, Wc)

#pragma unroll
    for (int an = 0; an < 8; an++) {
        const int jc = an * 8 + fcol * 2;
        const float bx = bias[j0 + jc];
        const float by = bias[j0 + jc + 1];
#pragma unroll
        for (int am = 0; am < 2; am++) {
#pragma unroll
            for (int rh = 0; rh < 2; rh++) {
                const int m = m0 + wm + am * 16 + frow + rh * 8;
                float2 o;
                o.x = acc[am][an][rh * 2 + 0] + bx;
                o.y = acc[am][an][rh * 2 + 1] + by;
                *reinterpret_cast<float2*>(&out[(size_t)m * DIMC + j0 + jc]) = o;
            }
        }
    }
}

// ---------------------------------------------------------------------------
// Kernel 2: per-(window, head) attention (R15 — at its MUFU floor; frozen).
// ---------------------------------------------------------------------------
#define QSTR 34
#define SST  52

__global__ __launch_bounds__(256)
void attn_kernel(float* __restrict__ attn_out)
{
    __shared__ float qs[NTOK * QSTR];
    __shared__ float ks[NTOK * QSTR];
    __shared__ float vs[NTOK * QSTR];
    __shared__ float S[NTOK * SST];

    const int bh  = blockIdx.x;
    const int b   = bh / NH;
    const int h   = bh - b * NH;
    const int tid = threadIdx.x;

    const size_t base2 = (size_t)bh * (NTOK * HD / 2);
    const float2* q2 = reinterpret_cast<const float2*>(g_q) + base2;
    const float2* k2 = reinterpret_cast<const float2*>(g_k) + base2;
    const float2* v2 = reinterpret_cast<const float2*>(g_v) + base2;
    for (int idx = tid; idx < NTOK * (HD / 2); idx += 256) {
        const int r = idx >> 4, dp = idx & 15;
        *reinterpret_cast<float2*>(&qs[r * QSTR + 2 * dp]) = q2[idx];
        *reinterpret_cast<float2*>(&ks[r * QSTR + 2 * dp]) = k2[idx];
        *reinterpret_cast<float2*>(&vs[r * QSTR + 2 * dp]) = v2[idx];
    }
    __syncthreads();

    const float* bm = g_bm + (size_t)((b & (NWIN - 1)) * NH + h) * (NTOK * BMS);
    if (tid < 13 * 13) {
        const int bi = tid / 13, bj = tid - 13 * (tid / 13);
        const int i0 = bi * 4, j0 = bj * 4;
        const u64* qp[4]; const u64* kp[4];
#pragma unroll
        for (int t = 0; t < 4; t++) {
            const int ri = (i0 + t < NTOK) ? (i0 + t) : (NTOK - 1);
            const int rj = (j0 + t < NTOK) ? (j0 + t) : (NTOK - 1);
            qp[t] = reinterpret_cast<const u64*>(&qs[ri * QSTR]);
            kp[t] = reinterpret_cast<const u64*>(&ks[rj * QSTR]);
        }
        u64 acc[4][4];
#pragma unroll
        for (int a = 0; a < 4; a++)
#pragma unroll
            for (int c = 0; c < 4; c++) acc[a][c] = 0ull;
#pragma unroll
        for (int d = 0; d < HD / 2; d++) {
            u64 qv[4], kv[4];
#pragma unroll
            for (int t = 0; t < 4; t++) { qv[t] = qp[t][d]; kv[t] = kp[t][d]; }
#pragma unroll
            for (int a = 0; a < 4; a++)
#pragma unroll
                for (int c = 0; c < 4; c++)
                    ffma2(acc[a][c], qv[a], kv[c]);
        }
#pragma unroll
        for (int a = 0; a < 4; a++) {
            const int i = i0 + a;
            if (i < NTOK) {
                const float4 bmv = *reinterpret_cast<const float4*>(&bm[i * BMS + j0]);
                const float bb[4] = {bmv.x, bmv.y, bmv.z, bmv.w};
#pragma unroll
                for (int c = 0; c < 4; c++) {
                    if (j0 + c < NTOK) {
                        float2 f = *reinterpret_cast<float2*>(&acc[a][c]);
                        S[i * SST + (j0 + c)] = f.x + f.y + bb[c];
                    }
                }
            }
        }
    }
    __syncthreads();

    const int lane = tid & 31;
    const int wid  = tid >> 5;
    for (int i = wid; i < NTOK; i += 8) {
        float* srow = &S[i * SST];
        const float e1 = __expf(srow[lane]);
        const float e2 = (lane < NTOK - 32) ? __expf(srow[lane + 32]) : 0.f;
        float sum = e1 + e2;
#pragma unroll
        for (int o = 16; o > 0; o >>= 1)
            sum += __shfl_xor_sync(0xffffffffu, sum, o);
        const float inv = 1.0f / sum;
        const float p1 = e1 * inv;
        const float p2 = e2 * inv;
        srow[lane] = p1;
        if (lane < NTOK - 32) srow[lane + 32] = p2;
        if (attn_out) {
            float* arow = attn_out + (size_t)bh * (NTOK * NTOK) + i * NTOK;
            arow[lane] = p1;
            if (lane < NTOK - 32) arow[lane + 32] = p2;
        }
    }
    __syncthreads();

    if (tid < 13 * 8) {
        const int rb = tid >> 3;
        const int dg = tid & 7;
        const int i0 = rb * 4;
        const int r1 = (i0 + 1 < NTOK) ? i0 + 1 : NTOK - 1;
        const int r2 = (i0 + 2 < NTOK) ? i0 + 2 : NTOK - 1;
        const int r3 = (i0 + 3 < NTOK) ? i0 + 3 : NTOK - 1;
        u64 c00 = 0, c01 = 0, c10 = 0, c11 = 0;
        u64 c20 = 0, c21 = 0, c30 = 0, c31 = 0;
#pragma unroll 7
        for (int j = 0; j < NTOK; j++) {
            const u64 v0 = *reinterpret_cast<const u64*>(&vs[j * QSTR + 4 * dg]);
            const u64 v1 = *reinterpret_cast<const u64*>(&vs[j * QSTR + 4 * dg + 2]);
            float2 t0; t0.x = S[i0 * SST + j]; t0.y = t0.x;
            float2 t1; t1.x = S[r1 * SST + j]; t1.y = t1.x;
            float2 t2; t2.x = S[r2 * SST + j]; t2.y = t2.x;
            float2 t3; t3.x = S[r3 * SST + j]; t3.y = t3.x;
            const u64 p0 = *reinterpret_cast<u64*>(&t0);
            const u64 p1 = *reinterpret_cast<u64*>(&t1);
            const u64 p2 = *reinterpret_cast<u64*>(&t2);
            const u64 p3 = *reinterpret_cast<u64*>(&t3);
            ffma2(c00, p0, v0); ffma2(c01, p0, v1);
            ffma2(c10, p1, v0); ffma2(c11, p1, v1);
            ffma2(c20, p2, v0); ffma2(c21, p2, v1);
            ffma2(c30, p3, v0); ffma2(c31, p3, v1);
        }
        const size_t ob = (size_t)b * NTOK * DIMC + h * HD + 4 * dg;
        u64 cc[4][2] = {{c00, c01}, {c10, c11}, {c20, c21}, {c30, c31}};
#pragma unroll
        for (int r = 0; r < 4; r++) {
            if (i0 + r < NTOK) {
                float2 lo = *reinterpret_cast<float2*>(&cc[r][0]);
                float2 hi = *reinterpret_cast<float2*>(&cc[r][1]);
                uint4 o;
                o.x = f2tf(lo.x); o.y = f2tf(lo.y);
                o.z = f2tf(hi.x); o.w = f2tf(hi.y);
                *reinterpret_cast<uint4*>(&g_ctx[ob + (size_t)(i0 + r) * DIMC]) = o;
            }
        }
    }
}

// ---------------------------------------------------------------------------
// Launch
// ---------------------------------------------------------------------------
extern "C" void kernel_launch(void* const* d_in, const int* in_sizes, int n_in,
                              void* d_out, int out_size)
{
    const float* x      = (const float*)d_in[0];
    const float* mask   = (const float*)d_in[1];
    const float* qkv_w  = (const float*)d_in[2];
    const float* qkv_b  = (const float*)d_in[3];
    const float* proj_w = (const float*)d_in[4];
    const float* proj_b = (const float*)d_in[5];
    const float* rpb    = (const float*)d_in[6];
    const int*   relidx = (const int*)d_in[7];

    float* out = (float*)d_out;
    const long OUT_ELEMS  = (long)B_ * NTOK * DIMC;          // 38,535,168
    const long ATTN_ELEMS = (long)B_ * NH * NTOK * NTOK;     // 59,006,976
    float* attn_out = nullptr;
    if ((long)out_size >= OUT_ELEMS + ATTN_ELEMS) attn_out = out + OUT_ELEMS;

    u32* d_xc;    cudaGetSymbolAddress((void**)&d_xc,    g_xc);
    u32* d_wqkv;  cudaGetSymbolAddress((void**)&d_wqkv,  g_wqkv);
    u32* d_wproj; cudaGetSymbolAddress((void**)&d_wproj, g_wproj);

    cvt_kernel<<<4096, 256>>>((const float4*)x, (uint4*)d_xc,
                              (int)(OUT_ELEMS / 4));
    cvt_kernel<<<108, 256>>>((const float4*)qkv_w, (uint4*)d_wqkv,
                             (3 * DIMC * DIMC) / 4);
    cvt_kernel<<<36, 256>>>((const float4*)proj_w, (uint4*)d_wproj,
                            (DIMC * DIMC) / 4);

    bias_kernel<<<NWIN * NH, 256>>>(mask, rpb, relidx);
    qkv_gemm_kernel<<<dim3(576 / BN, (B_ * NTOK) / BM), 128>>>(qkv_b);
    attn_kernel<<<B_ * NH, 256>>>(attn_out);
    proj_gemm_kernel<<<dim3(DIMC / BN, (B_ * NTOK) / BM), 128>>>(proj_b, out);

    (void)in_sizes; (void)n_in;
}